// round 7
// baseline (speedup 1.0000x reference)
#include <cuda_runtime.h>
#include <cstdint>

// Problem constants
#define N_      128
#define L_      1024
#define C_      512
#define LCAT_   2045                    // 1023 + 1022
#define INV_TEMP 14.285714285714285f    // 1 / 0.07

// Scratch: pred[l][m][c] for the current step (max Ls = 1023). 268 MB.
__device__ float g_pred[1023u * 128u * 512u];
__device__ unsigned int g_count[2];

// ---------------------------------------------------------------------------
// f32x2 packed helpers (sm_103a FFMA2 path — PTX-only)
// ---------------------------------------------------------------------------
__device__ __forceinline__ unsigned long long pack2(float lo, float hi) {
    unsigned long long r;
    asm("mov.b64 %0, {%1, %2};"
        : "=l"(r) : "r"(__float_as_uint(lo)), "r"(__float_as_uint(hi)));
    return r;
}
__device__ __forceinline__ void unpack2(unsigned long long v, float& lo, float& hi) {
    unsigned int a, b;
    asm("mov.b64 {%0, %1}, %2;" : "=r"(a), "=r"(b) : "l"(v));
    lo = __uint_as_float(a);
    hi = __uint_as_float(b);
}
__device__ __forceinline__ void ffma2(unsigned long long& d,
                                      unsigned long long a,
                                      unsigned long long b) {
    asm("fma.rn.f32x2 %0, %1, %2, %0;" : "+l"(d) : "l"(a), "l"(b));
}

// ===========================================================================
// Kernel 1: pred[l][m][c] = sum_k P[m][l][k] * W[c][k] + b[c]
//   Block tile 128(m) x 256(c), BK=16, double-buffered, 256 threads.
//   Thread tile 8x16: rows {ty*4, 64+ty*4}+0..3, cols {q*64 + tx*4}+0..3, q=0..3
//   smem/FLOP = 0.375 B (under the 128 B/cyc crossbar at FFMA2 peak).
//   grid = (2 c-tiles, Ls)
// ===========================================================================
__global__ __launch_bounds__(256, 1)
void pred_gemm(const float* __restrict__ P, const float* __restrict__ W,
               const float* __restrict__ bias)
{
    const int l  = blockIdx.y;
    const int c0 = blockIdx.x * 256;

    __shared__ float As[2][16][128];
    __shared__ float Bs[2][16][256];

    const int tid = threadIdx.x;
    const int tx  = tid & 15;
    const int ty  = tid >> 4;

    unsigned long long acc[8][8];
#pragma unroll
    for (int i = 0; i < 8; i++)
#pragma unroll
        for (int j = 0; j < 8; j++) acc[i][j] = 0ull;

    const float* Abase = P + (size_t)l * C_;      // + m*(L_*C_) + k
    const float* Bbase = W + (size_t)c0 * C_;     // + c*C_ + k

    // A: 512 float4 per tile -> 2/thread ; B: 1024 float4 -> 4/thread
    const int ar0 = tid >> 2;            // 0..63
    const int ar1 = 64 + ar0;
    const int akq = (tid & 3) * 4;

    // Preload tile 0
    {
        float4 va0 = *(const float4*)(Abase + (size_t)ar0 * (L_ * C_) + akq);
        float4 va1 = *(const float4*)(Abase + (size_t)ar1 * (L_ * C_) + akq);
        As[0][akq+0][ar0]=va0.x; As[0][akq+1][ar0]=va0.y; As[0][akq+2][ar0]=va0.z; As[0][akq+3][ar0]=va0.w;
        As[0][akq+0][ar1]=va1.x; As[0][akq+1][ar1]=va1.y; As[0][akq+2][ar1]=va1.z; As[0][akq+3][ar1]=va1.w;
#pragma unroll
        for (int t = 0; t < 4; t++) {
            int e   = tid + t * 256;
            int row = e >> 2;            // 0..255
            int kq  = (e & 3) * 4;
            float4 vb = *(const float4*)(Bbase + (size_t)row * C_ + kq);
            Bs[0][kq+0][row]=vb.x; Bs[0][kq+1][row]=vb.y; Bs[0][kq+2][row]=vb.z; Bs[0][kq+3][row]=vb.w;
        }
    }
    __syncthreads();

    int buf = 0;
    for (int k0 = 16; k0 < C_; k0 += 16) {
        // Prefetch next tile into registers
        float4 va0 = *(const float4*)(Abase + (size_t)ar0 * (L_ * C_) + k0 + akq);
        float4 va1 = *(const float4*)(Abase + (size_t)ar1 * (L_ * C_) + k0 + akq);
        float4 vb[4];
#pragma unroll
        for (int t = 0; t < 4; t++) {
            int e   = tid + t * 256;
            int row = e >> 2;
            int kq  = (e & 3) * 4;
            vb[t] = *(const float4*)(Bbase + (size_t)row * C_ + k0 + kq);
        }

        // Compute on current buffer
#pragma unroll
        for (int k = 0; k < 16; k++) {
            float4 a0 = *(const float4*)&As[buf][k][ty * 4];
            float4 a1 = *(const float4*)&As[buf][k][64 + ty * 4];
            unsigned long long b2[8];
#pragma unroll
            for (int q = 0; q < 4; q++) {
                ulonglong2 bb = *(const ulonglong2*)&Bs[buf][k][q * 64 + tx * 4];
                b2[2 * q] = bb.x; b2[2 * q + 1] = bb.y;
            }
            float af[8] = { a0.x, a0.y, a0.z, a0.w, a1.x, a1.y, a1.z, a1.w };
#pragma unroll
            for (int i = 0; i < 8; i++) {
                unsigned long long a2 = pack2(af[i], af[i]);
#pragma unroll
                for (int j = 0; j < 8; j++) ffma2(acc[i][j], a2, b2[j]);
            }
        }

        const int nb = buf ^ 1;
        As[nb][akq+0][ar0]=va0.x; As[nb][akq+1][ar0]=va0.y; As[nb][akq+2][ar0]=va0.z; As[nb][akq+3][ar0]=va0.w;
        As[nb][akq+0][ar1]=va1.x; As[nb][akq+1][ar1]=va1.y; As[nb][akq+2][ar1]=va1.z; As[nb][akq+3][ar1]=va1.w;
#pragma unroll
        for (int t = 0; t < 4; t++) {
            int e   = tid + t * 256;
            int row = e >> 2;
            int kq  = (e & 3) * 4;
            Bs[nb][kq+0][row]=vb[t].x; Bs[nb][kq+1][row]=vb[t].y;
            Bs[nb][kq+2][row]=vb[t].z; Bs[nb][kq+3][row]=vb[t].w;
        }
        __syncthreads();
        buf = nb;
    }
    // Last tile
#pragma unroll
    for (int k = 0; k < 16; k++) {
        float4 a0 = *(const float4*)&As[buf][k][ty * 4];
        float4 a1 = *(const float4*)&As[buf][k][64 + ty * 4];
        unsigned long long b2[8];
#pragma unroll
        for (int q = 0; q < 4; q++) {
            ulonglong2 bb = *(const ulonglong2*)&Bs[buf][k][q * 64 + tx * 4];
            b2[2 * q] = bb.x; b2[2 * q + 1] = bb.y;
        }
        float af[8] = { a0.x, a0.y, a0.z, a0.w, a1.x, a1.y, a1.z, a1.w };
#pragma unroll
        for (int i = 0; i < 8; i++) {
            unsigned long long a2 = pack2(af[i], af[i]);
#pragma unroll
            for (int j = 0; j < 8; j++) ffma2(acc[i][j], a2, b2[j]);
        }
    }

    // Epilogue: + bias, store pred[l][m][c]
    float bf[16];
#pragma unroll
    for (int q = 0; q < 4; q++)
#pragma unroll
        for (int j = 0; j < 4; j++)
            bf[4 * q + j] = bias[c0 + q * 64 + tx * 4 + j];

    float* out = g_pred + (size_t)l * N_ * C_ + c0;
#pragma unroll
    for (int i = 0; i < 8; i++) {
        const int m = (i < 4) ? (ty * 4 + i) : (64 + ty * 4 + (i - 4));
        float v[16];
#pragma unroll
        for (int j = 0; j < 8; j++) unpack2(acc[i][j], v[2 * j], v[2 * j + 1]);
#pragma unroll
        for (int j = 0; j < 16; j++) v[j] += bf[j];
#pragma unroll
        for (int q = 0; q < 4; q++) {
            *(float4*)(out + (size_t)m * C_ + q * 64 + tx * 4) =
                make_float4(v[4 * q], v[4 * q + 1], v[4 * q + 2], v[4 * q + 3]);
        }
    }
}

// ===========================================================================
// Kernel 2: per-l 128x128 GEMM  l_neg[n][m] = sum_k T[n][l+step][k]*pred[l][m][k]
//   + fused NCE accuracy + scaled logits store. grid = Ls, block = 256
// ===========================================================================
__device__ __forceinline__ void compute_tile8(
    const float (*As)[128], const float (*Bs)[128],
    int tx, int ty, unsigned long long (&acc)[8][4])
{
#pragma unroll
    for (int k = 0; k < 16; k++) {
        float4 a0 = *(const float4*)&As[k][ty * 4];
        float4 a1 = *(const float4*)&As[k][64 + ty * 4];
        ulonglong2 bb0 = *(const ulonglong2*)&Bs[k][tx * 4];
        ulonglong2 bb1 = *(const ulonglong2*)&Bs[k][64 + tx * 4];
        unsigned long long b2[4] = { bb0.x, bb0.y, bb1.x, bb1.y };
        float af[8] = { a0.x, a0.y, a0.z, a0.w, a1.x, a1.y, a1.z, a1.w };
#pragma unroll
        for (int i = 0; i < 8; i++) {
            unsigned long long a2 = pack2(af[i], af[i]);
            ffma2(acc[i][0], a2, b2[0]);
            ffma2(acc[i][1], a2, b2[1]);
            ffma2(acc[i][2], a2, b2[2]);
            ffma2(acc[i][3], a2, b2[3]);
        }
    }
}

__global__ __launch_bounds__(256, 2)
void lneg_gemm(const float* __restrict__ T, int step, int lofs, int cntIdx,
               float* __restrict__ outLogits)
{
    const int l = blockIdx.x;

    __shared__ float As[2][16][128];
    __shared__ float Bs[2][16][128];
    __shared__ float spos[N_];
    __shared__ unsigned int sflag[N_];

    const int tid = threadIdx.x;
    const int tx  = tid & 15;
    const int ty  = tid >> 4;

    unsigned long long acc[8][4];
#pragma unroll
    for (int i = 0; i < 8; i++)
#pragma unroll
        for (int j = 0; j < 4; j++) acc[i][j] = 0ull;

    const float* Abase = T + (size_t)(l + step) * C_;       // + n*(L_*C_) + k
    const float* Bbase = g_pred + (size_t)l * N_ * C_;      // + m*C_ + k

    const int r0 = tid >> 2;
    const int r1 = 64 + r0;
    const int kq = (tid & 3) * 4;

    {
        float4 va0 = *(const float4*)(Abase + (size_t)r0 * (L_ * C_) + kq);
        float4 va1 = *(const float4*)(Abase + (size_t)r1 * (L_ * C_) + kq);
        float4 vb0 = *(const float4*)(Bbase + (size_t)r0 * C_ + kq);
        float4 vb1 = *(const float4*)(Bbase + (size_t)r1 * C_ + kq);
        As[0][kq+0][r0]=va0.x; As[0][kq+1][r0]=va0.y; As[0][kq+2][r0]=va0.z; As[0][kq+3][r0]=va0.w;
        As[0][kq+0][r1]=va1.x; As[0][kq+1][r1]=va1.y; As[0][kq+2][r1]=va1.z; As[0][kq+3][r1]=va1.w;
        Bs[0][kq+0][r0]=vb0.x; Bs[0][kq+1][r0]=vb0.y; Bs[0][kq+2][r0]=vb0.z; Bs[0][kq+3][r0]=vb0.w;
        Bs[0][kq+0][r1]=vb1.x; Bs[0][kq+1][r1]=vb1.y; Bs[0][kq+2][r1]=vb1.z; Bs[0][kq+3][r1]=vb1.w;
    }
    __syncthreads();

    int buf = 0;
    for (int k0 = 16; k0 < C_; k0 += 16) {
        float4 va0 = *(const float4*)(Abase + (size_t)r0 * (L_ * C_) + k0 + kq);
        float4 va1 = *(const float4*)(Abase + (size_t)r1 * (L_ * C_) + k0 + kq);
        float4 vb0 = *(const float4*)(Bbase + (size_t)r0 * C_ + k0 + kq);
        float4 vb1 = *(const float4*)(Bbase + (size_t)r1 * C_ + k0 + kq);

        compute_tile8(As[buf], Bs[buf], tx, ty, acc);

        const int nb = buf ^ 1;
        As[nb][kq+0][r0]=va0.x; As[nb][kq+1][r0]=va0.y; As[nb][kq+2][r0]=va0.z; As[nb][kq+3][r0]=va0.w;
        As[nb][kq+0][r1]=va1.x; As[nb][kq+1][r1]=va1.y; As[nb][kq+2][r1]=va1.z; As[nb][kq+3][r1]=va1.w;
        Bs[nb][kq+0][r0]=vb0.x; Bs[nb][kq+1][r0]=vb0.y; Bs[nb][kq+2][r0]=vb0.z; Bs[nb][kq+3][r0]=vb0.w;
        Bs[nb][kq+0][r1]=vb1.x; Bs[nb][kq+1][r1]=vb1.y; Bs[nb][kq+2][r1]=vb1.z; Bs[nb][kq+3][r1]=vb1.w;
        __syncthreads();
        buf = nb;
    }
    compute_tile8(As[buf], Bs[buf], tx, ty, acc);

    // Unpack raw l_neg values
    float v[8][8];
#pragma unroll
    for (int i = 0; i < 8; i++)
#pragma unroll
        for (int j = 0; j < 4; j++) unpack2(acc[i][j], v[i][2 * j], v[i][2 * j + 1]);

    int rown[8], colm[8];
#pragma unroll
    for (int i = 0; i < 4; i++) {
        rown[i] = ty * 4 + i;      rown[4 + i] = 64 + ty * 4 + i;
        colm[i] = tx * 4 + i;      colm[4 + i] = 64 + tx * 4 + i;
    }

    // Fused NCE accuracy
    if (tid < N_) sflag[tid] = 1u;
    if (tx == ty) {
#pragma unroll
        for (int i = 0; i < 4; i++) {
            spos[ty * 4 + i]      = v[i][i];
            spos[64 + ty * 4 + i] = v[4 + i][4 + i];
        }
    }
    __syncthreads();

#pragma unroll
    for (int i = 0; i < 8; i++) {
        const int n = rown[i];
        const float pos = spos[n];
        unsigned int ok = 1u;
#pragma unroll
        for (int j = 0; j < 8; j++) {
            if (colm[j] != n) ok &= (pos > v[i][j]) ? 1u : 0u;
        }
        if (!ok) atomicAnd(&sflag[n], 0u);
    }
    __syncthreads();

    if (tid == 0) {
        unsigned int c = 0;
#pragma unroll 4
        for (int n = 0; n < N_; n++) c += sflag[n];
        atomicAdd(&g_count[cntIdx], c);
    }

    // Store scaled logits: out[n][m][lofs + l]
#pragma unroll
    for (int i = 0; i < 8; i++) {
        float* rowp = outLogits + (size_t)rown[i] * ((size_t)N_ * LCAT_)
                                + (size_t)(lofs + l);
#pragma unroll
        for (int j = 0; j < 8; j++) {
            rowp[(size_t)colm[j] * LCAT_] = v[i][j] * INV_TEMP;
        }
    }
}

// ---------------------------------------------------------------------------
// Init: zero counters + fill y_trues region (as float)
// ---------------------------------------------------------------------------
__global__ void init_kernel(float* __restrict__ out)
{
    if (blockIdx.x == 0 && threadIdx.x < 2) g_count[threadIdx.x] = 0u;
    const size_t idx = (size_t)blockIdx.x * 256 + threadIdx.x;
    const size_t yN  = (size_t)N_ * LCAT_;
    if (idx < yN) {
        const size_t base = (size_t)N_ * N_ * LCAT_;
        out[base + idx] = (float)(idx / LCAT_);
    }
}

// ---------------------------------------------------------------------------
// Finalize: accs
// ---------------------------------------------------------------------------
__global__ void fin_kernel(float* __restrict__ out)
{
    if (threadIdx.x == 0) {
        const size_t base = (size_t)N_ * N_ * LCAT_ + (size_t)N_ * LCAT_;
        out[base + 0] = (float)g_count[0] / (float)(N_ * 1023);
        out[base + 1] = (float)g_count[1] / (float)(N_ * 1022);
    }
}

// ---------------------------------------------------------------------------
// Launch
// ---------------------------------------------------------------------------
extern "C" void kernel_launch(void* const* d_in, const int* in_sizes, int n_in,
                              void* d_out, int out_size)
{
    const float* ts = (const float*)d_in[0];   // timesteps         (N, L, C)
    const float* ps = (const float*)d_in[1];   // patient_timesteps (N, L, C)
    const float* W1 = (const float*)d_in[2];   // (C, C)
    const float* b1 = (const float*)d_in[3];   // (C,)
    const float* W2 = (const float*)d_in[4];   // (C, C)
    const float* b2 = (const float*)d_in[5];   // (C,)
    float* out = (float*)d_out;

    init_kernel<<<1023, 256>>>(out);

    // Step 1 (Ls = 1023), logits columns [0, 1023)
    {
        dim3 g(2, 1023);
        pred_gemm<<<g, 256>>>(ps, W1, b1);
        lneg_gemm<<<1023, 256>>>(ts, 1, 0, 0, out);
    }
    // Step 2 (Ls = 1022), logits columns [1023, 2045)
    {
        dim3 g(2, 1022);
        pred_gemm<<<g, 256>>>(ps, W2, b2);
        lneg_gemm<<<1022, 256>>>(ts, 2, 1023, 1, out);
    }

    fin_kernel<<<1, 32>>>(out);
}

// round 8
// speedup vs baseline: 1.0004x; 1.0004x over previous
#include <cuda_runtime.h>
#include <cstdint>

// Problem constants
#define N_      128
#define L_      1024
#define C_      512
#define LCAT_   2045                    // 1023 + 1022
#define INV_TEMP 14.285714285714285f    // 1 / 0.07

// Scratch: pred[l][m][c] for the current step (max Ls = 1023). 268 MB.
__device__ float g_pred[1023u * 128u * 512u];
__device__ unsigned int g_count[2];

// ---------------------------------------------------------------------------
// f32x2 packed helpers (sm_103a FFMA2 path — PTX-only)
// ---------------------------------------------------------------------------
__device__ __forceinline__ unsigned long long pack2(float lo, float hi) {
    unsigned long long r;
    asm("mov.b64 %0, {%1, %2};"
        : "=l"(r) : "r"(__float_as_uint(lo)), "r"(__float_as_uint(hi)));
    return r;
}
__device__ __forceinline__ void unpack2(unsigned long long v, float& lo, float& hi) {
    unsigned int a, b;
    asm("mov.b64 {%0, %1}, %2;" : "=r"(a), "=r"(b) : "l"(v));
    lo = __uint_as_float(a);
    hi = __uint_as_float(b);
}
__device__ __forceinline__ void ffma2(unsigned long long& d,
                                      unsigned long long a,
                                      unsigned long long b) {
    asm("fma.rn.f32x2 %0, %1, %2, %0;" : "+l"(d) : "l"(a), "l"(b));
}

// ===========================================================================
// Kernel 1: pred[l][m][c] = sum_k P[m][l][k] * W[c][k] + b[c]
//   Block tile 128(m) x 256(c), BK=16, double-buffered, 256 threads.
//   Thread tile 8x16: rows {ty*4, 64+ty*4}+0..3, cols {q*64 + tx*4}+0..3, q=0..3
//   smem/FLOP = 0.375 B (under the 128 B/cyc crossbar at FFMA2 peak).
//   grid = (2 c-tiles, Ls)
// ===========================================================================
__global__ __launch_bounds__(256, 1)
void pred_gemm(const float* __restrict__ P, const float* __restrict__ W,
               const float* __restrict__ bias)
{
    const int l  = blockIdx.y;
    const int c0 = blockIdx.x * 256;

    __shared__ float As[2][16][128];
    __shared__ float Bs[2][16][256];

    const int tid = threadIdx.x;
    const int tx  = tid & 15;
    const int ty  = tid >> 4;

    unsigned long long acc[8][8];
#pragma unroll
    for (int i = 0; i < 8; i++)
#pragma unroll
        for (int j = 0; j < 8; j++) acc[i][j] = 0ull;

    const float* Abase = P + (size_t)l * C_;      // + m*(L_*C_) + k
    const float* Bbase = W + (size_t)c0 * C_;     // + c*C_ + k

    // A: 512 float4 per tile -> 2/thread ; B: 1024 float4 -> 4/thread
    const int ar0 = tid >> 2;            // 0..63
    const int ar1 = 64 + ar0;
    const int akq = (tid & 3) * 4;

    // Preload tile 0
    {
        float4 va0 = *(const float4*)(Abase + (size_t)ar0 * (L_ * C_) + akq);
        float4 va1 = *(const float4*)(Abase + (size_t)ar1 * (L_ * C_) + akq);
        As[0][akq+0][ar0]=va0.x; As[0][akq+1][ar0]=va0.y; As[0][akq+2][ar0]=va0.z; As[0][akq+3][ar0]=va0.w;
        As[0][akq+0][ar1]=va1.x; As[0][akq+1][ar1]=va1.y; As[0][akq+2][ar1]=va1.z; As[0][akq+3][ar1]=va1.w;
#pragma unroll
        for (int t = 0; t < 4; t++) {
            int e   = tid + t * 256;
            int row = e >> 2;            // 0..255
            int kq  = (e & 3) * 4;
            float4 vb = *(const float4*)(Bbase + (size_t)row * C_ + kq);
            Bs[0][kq+0][row]=vb.x; Bs[0][kq+1][row]=vb.y; Bs[0][kq+2][row]=vb.z; Bs[0][kq+3][row]=vb.w;
        }
    }
    __syncthreads();

    int buf = 0;
    for (int k0 = 16; k0 < C_; k0 += 16) {
        // Prefetch next tile into registers
        float4 va0 = *(const float4*)(Abase + (size_t)ar0 * (L_ * C_) + k0 + akq);
        float4 va1 = *(const float4*)(Abase + (size_t)ar1 * (L_ * C_) + k0 + akq);
        float4 vb[4];
#pragma unroll
        for (int t = 0; t < 4; t++) {
            int e   = tid + t * 256;
            int row = e >> 2;
            int kq  = (e & 3) * 4;
            vb[t] = *(const float4*)(Bbase + (size_t)row * C_ + k0 + kq);
        }

        // Compute on current buffer
#pragma unroll
        for (int k = 0; k < 16; k++) {
            float4 a0 = *(const float4*)&As[buf][k][ty * 4];
            float4 a1 = *(const float4*)&As[buf][k][64 + ty * 4];
            unsigned long long b2[8];
#pragma unroll
            for (int q = 0; q < 4; q++) {
                ulonglong2 bb = *(const ulonglong2*)&Bs[buf][k][q * 64 + tx * 4];
                b2[2 * q] = bb.x; b2[2 * q + 1] = bb.y;
            }
            float af[8] = { a0.x, a0.y, a0.z, a0.w, a1.x, a1.y, a1.z, a1.w };
#pragma unroll
            for (int i = 0; i < 8; i++) {
                unsigned long long a2 = pack2(af[i], af[i]);
#pragma unroll
                for (int j = 0; j < 8; j++) ffma2(acc[i][j], a2, b2[j]);
            }
        }

        const int nb = buf ^ 1;
        As[nb][akq+0][ar0]=va0.x; As[nb][akq+1][ar0]=va0.y; As[nb][akq+2][ar0]=va0.z; As[nb][akq+3][ar0]=va0.w;
        As[nb][akq+0][ar1]=va1.x; As[nb][akq+1][ar1]=va1.y; As[nb][akq+2][ar1]=va1.z; As[nb][akq+3][ar1]=va1.w;
#pragma unroll
        for (int t = 0; t < 4; t++) {
            int e   = tid + t * 256;
            int row = e >> 2;
            int kq  = (e & 3) * 4;
            Bs[nb][kq+0][row]=vb[t].x; Bs[nb][kq+1][row]=vb[t].y;
            Bs[nb][kq+2][row]=vb[t].z; Bs[nb][kq+3][row]=vb[t].w;
        }
        __syncthreads();
        buf = nb;
    }
    // Last tile
#pragma unroll
    for (int k = 0; k < 16; k++) {
        float4 a0 = *(const float4*)&As[buf][k][ty * 4];
        float4 a1 = *(const float4*)&As[buf][k][64 + ty * 4];
        unsigned long long b2[8];
#pragma unroll
        for (int q = 0; q < 4; q++) {
            ulonglong2 bb = *(const ulonglong2*)&Bs[buf][k][q * 64 + tx * 4];
            b2[2 * q] = bb.x; b2[2 * q + 1] = bb.y;
        }
        float af[8] = { a0.x, a0.y, a0.z, a0.w, a1.x, a1.y, a1.z, a1.w };
#pragma unroll
        for (int i = 0; i < 8; i++) {
            unsigned long long a2 = pack2(af[i], af[i]);
#pragma unroll
            for (int j = 0; j < 8; j++) ffma2(acc[i][j], a2, b2[j]);
        }
    }

    // Epilogue: + bias, store pred[l][m][c]
    float bf[16];
#pragma unroll
    for (int q = 0; q < 4; q++)
#pragma unroll
        for (int j = 0; j < 4; j++)
            bf[4 * q + j] = bias[c0 + q * 64 + tx * 4 + j];

    float* out = g_pred + (size_t)l * N_ * C_ + c0;
#pragma unroll
    for (int i = 0; i < 8; i++) {
        const int m = (i < 4) ? (ty * 4 + i) : (64 + ty * 4 + (i - 4));
        float v[16];
#pragma unroll
        for (int j = 0; j < 8; j++) unpack2(acc[i][j], v[2 * j], v[2 * j + 1]);
#pragma unroll
        for (int j = 0; j < 16; j++) v[j] += bf[j];
#pragma unroll
        for (int q = 0; q < 4; q++) {
            *(float4*)(out + (size_t)m * C_ + q * 64 + tx * 4) =
                make_float4(v[4 * q], v[4 * q + 1], v[4 * q + 2], v[4 * q + 3]);
        }
    }
}

// ===========================================================================
// Kernel 2: per-l 128x128 GEMM  l_neg[n][m] = sum_k T[n][l+step][k]*pred[l][m][k]
//   + fused NCE accuracy + scaled logits store. grid = Ls, block = 256
// ===========================================================================
__device__ __forceinline__ void compute_tile8(
    const float (*As)[128], const float (*Bs)[128],
    int tx, int ty, unsigned long long (&acc)[8][4])
{
#pragma unroll
    for (int k = 0; k < 16; k++) {
        float4 a0 = *(const float4*)&As[k][ty * 4];
        float4 a1 = *(const float4*)&As[k][64 + ty * 4];
        ulonglong2 bb0 = *(const ulonglong2*)&Bs[k][tx * 4];
        ulonglong2 bb1 = *(const ulonglong2*)&Bs[k][64 + tx * 4];
        unsigned long long b2[4] = { bb0.x, bb0.y, bb1.x, bb1.y };
        float af[8] = { a0.x, a0.y, a0.z, a0.w, a1.x, a1.y, a1.z, a1.w };
#pragma unroll
        for (int i = 0; i < 8; i++) {
            unsigned long long a2 = pack2(af[i], af[i]);
            ffma2(acc[i][0], a2, b2[0]);
            ffma2(acc[i][1], a2, b2[1]);
            ffma2(acc[i][2], a2, b2[2]);
            ffma2(acc[i][3], a2, b2[3]);
        }
    }
}

__global__ __launch_bounds__(256, 2)
void lneg_gemm(const float* __restrict__ T, int step, int lofs, int cntIdx,
               float* __restrict__ outLogits)
{
    const int l = blockIdx.x;

    __shared__ float As[2][16][128];
    __shared__ float Bs[2][16][128];
    __shared__ float spos[N_];
    __shared__ unsigned int sflag[N_];

    const int tid = threadIdx.x;
    const int tx  = tid & 15;
    const int ty  = tid >> 4;

    unsigned long long acc[8][4];
#pragma unroll
    for (int i = 0; i < 8; i++)
#pragma unroll
        for (int j = 0; j < 4; j++) acc[i][j] = 0ull;

    const float* Abase = T + (size_t)(l + step) * C_;       // + n*(L_*C_) + k
    const float* Bbase = g_pred + (size_t)l * N_ * C_;      // + m*C_ + k

    const int r0 = tid >> 2;
    const int r1 = 64 + r0;
    const int kq = (tid & 3) * 4;

    {
        float4 va0 = *(const float4*)(Abase + (size_t)r0 * (L_ * C_) + kq);
        float4 va1 = *(const float4*)(Abase + (size_t)r1 * (L_ * C_) + kq);
        float4 vb0 = *(const float4*)(Bbase + (size_t)r0 * C_ + kq);
        float4 vb1 = *(const float4*)(Bbase + (size_t)r1 * C_ + kq);
        As[0][kq+0][r0]=va0.x; As[0][kq+1][r0]=va0.y; As[0][kq+2][r0]=va0.z; As[0][kq+3][r0]=va0.w;
        As[0][kq+0][r1]=va1.x; As[0][kq+1][r1]=va1.y; As[0][kq+2][r1]=va1.z; As[0][kq+3][r1]=va1.w;
        Bs[0][kq+0][r0]=vb0.x; Bs[0][kq+1][r0]=vb0.y; Bs[0][kq+2][r0]=vb0.z; Bs[0][kq+3][r0]=vb0.w;
        Bs[0][kq+0][r1]=vb1.x; Bs[0][kq+1][r1]=vb1.y; Bs[0][kq+2][r1]=vb1.z; Bs[0][kq+3][r1]=vb1.w;
    }
    __syncthreads();

    int buf = 0;
    for (int k0 = 16; k0 < C_; k0 += 16) {
        float4 va0 = *(const float4*)(Abase + (size_t)r0 * (L_ * C_) + k0 + kq);
        float4 va1 = *(const float4*)(Abase + (size_t)r1 * (L_ * C_) + k0 + kq);
        float4 vb0 = *(const float4*)(Bbase + (size_t)r0 * C_ + k0 + kq);
        float4 vb1 = *(const float4*)(Bbase + (size_t)r1 * C_ + k0 + kq);

        compute_tile8(As[buf], Bs[buf], tx, ty, acc);

        const int nb = buf ^ 1;
        As[nb][kq+0][r0]=va0.x; As[nb][kq+1][r0]=va0.y; As[nb][kq+2][r0]=va0.z; As[nb][kq+3][r0]=va0.w;
        As[nb][kq+0][r1]=va1.x; As[nb][kq+1][r1]=va1.y; As[nb][kq+2][r1]=va1.z; As[nb][kq+3][r1]=va1.w;
        Bs[nb][kq+0][r0]=vb0.x; Bs[nb][kq+1][r0]=vb0.y; Bs[nb][kq+2][r0]=vb0.z; Bs[nb][kq+3][r0]=vb0.w;
        Bs[nb][kq+0][r1]=vb1.x; Bs[nb][kq+1][r1]=vb1.y; Bs[nb][kq+2][r1]=vb1.z; Bs[nb][kq+3][r1]=vb1.w;
        __syncthreads();
        buf = nb;
    }
    compute_tile8(As[buf], Bs[buf], tx, ty, acc);

    // Unpack raw l_neg values
    float v[8][8];
#pragma unroll
    for (int i = 0; i < 8; i++)
#pragma unroll
        for (int j = 0; j < 4; j++) unpack2(acc[i][j], v[i][2 * j], v[i][2 * j + 1]);

    int rown[8], colm[8];
#pragma unroll
    for (int i = 0; i < 4; i++) {
        rown[i] = ty * 4 + i;      rown[4 + i] = 64 + ty * 4 + i;
        colm[i] = tx * 4 + i;      colm[4 + i] = 64 + tx * 4 + i;
    }

    // Fused NCE accuracy
    if (tid < N_) sflag[tid] = 1u;
    if (tx == ty) {
#pragma unroll
        for (int i = 0; i < 4; i++) {
            spos[ty * 4 + i]      = v[i][i];
            spos[64 + ty * 4 + i] = v[4 + i][4 + i];
        }
    }
    __syncthreads();

#pragma unroll
    for (int i = 0; i < 8; i++) {
        const int n = rown[i];
        const float pos = spos[n];
        unsigned int ok = 1u;
#pragma unroll
        for (int j = 0; j < 8; j++) {
            if (colm[j] != n) ok &= (pos > v[i][j]) ? 1u : 0u;
        }
        if (!ok) atomicAnd(&sflag[n], 0u);
    }
    __syncthreads();

    if (tid == 0) {
        unsigned int c = 0;
#pragma unroll 4
        for (int n = 0; n < N_; n++) c += sflag[n];
        atomicAdd(&g_count[cntIdx], c);
    }

    // Store scaled logits: out[n][m][lofs + l]
#pragma unroll
    for (int i = 0; i < 8; i++) {
        float* rowp = outLogits + (size_t)rown[i] * ((size_t)N_ * LCAT_)
                                + (size_t)(lofs + l);
#pragma unroll
        for (int j = 0; j < 8; j++) {
            rowp[(size_t)colm[j] * LCAT_] = v[i][j] * INV_TEMP;
        }
    }
}

// ---------------------------------------------------------------------------
// Init: zero counters + fill y_trues region (as float)
// ---------------------------------------------------------------------------
__global__ void init_kernel(float* __restrict__ out)
{
    if (blockIdx.x == 0 && threadIdx.x < 2) g_count[threadIdx.x] = 0u;
    const size_t idx = (size_t)blockIdx.x * 256 + threadIdx.x;
    const size_t yN  = (size_t)N_ * LCAT_;
    if (idx < yN) {
        const size_t base = (size_t)N_ * N_ * LCAT_;
        out[base + idx] = (float)(idx / LCAT_);
    }
}

// ---------------------------------------------------------------------------
// Finalize: accs
// ---------------------------------------------------------------------------
__global__ void fin_kernel(float* __restrict__ out)
{
    if (threadIdx.x == 0) {
        const size_t base = (size_t)N_ * N_ * LCAT_ + (size_t)N_ * LCAT_;
        out[base + 0] = (float)g_count[0] / (float)(N_ * 1023);
        out[base + 1] = (float)g_count[1] / (float)(N_ * 1022);
    }
}

// ---------------------------------------------------------------------------
// Launch
// ---------------------------------------------------------------------------
extern "C" void kernel_launch(void* const* d_in, const int* in_sizes, int n_in,
                              void* d_out, int out_size)
{
    const float* ts = (const float*)d_in[0];   // timesteps         (N, L, C)
    const float* ps = (const float*)d_in[1];   // patient_timesteps (N, L, C)
    const float* W1 = (const float*)d_in[2];   // (C, C)
    const float* b1 = (const float*)d_in[3];   // (C,)
    const float* W2 = (const float*)d_in[4];   // (C, C)
    const float* b2 = (const float*)d_in[5];   // (C,)
    float* out = (float*)d_out;

    init_kernel<<<1023, 256>>>(out);

    // Step 1 (Ls = 1023), logits columns [0, 1023)
    {
        dim3 g(2, 1023);
        pred_gemm<<<g, 256>>>(ps, W1, b1);
        lneg_gemm<<<1023, 256>>>(ts, 1, 0, 0, out);
    }
    // Step 2 (Ls = 1022), logits columns [1023, 2045)
    {
        dim3 g(2, 1022);
        pred_gemm<<<g, 256>>>(ps, W2, b2);
        lneg_gemm<<<1022, 256>>>(ts, 2, 1023, 1, out);
    }

    fin_kernel<<<1, 32>>>(out);
}

// round 10
// speedup vs baseline: 2.1196x; 2.1187x over previous
#include <cuda_runtime.h>
#include <cuda_bf16.h>
#include <cstdint>

#define N_      128
#define L_      1024
#define C_      512
#define LCAT_   2045
#define INV_TEMP 14.285714285714285f
#define NM_     16384
#define SMEM_DYN 66560   // max(64KB tiles, 128*130*4 epilogue buffer)

__device__ float g_pred[1024u * 128u * 512u];          // pred[l][m][c], fp32
__device__ float g_scr[(size_t)LCAT_ * NM_];           // logits scratch [lg][n][m]
__device__ unsigned int g_count[2];

// ---------------------------------------------------------------------------
// Helpers (base-target PTX only: ldmatrix + mma.sync, no 'a' features)
// ---------------------------------------------------------------------------
__device__ __forceinline__ uint32_t smem_u32(const void* p) {
    uint32_t a;
    asm("{ .reg .u64 t; cvta.to.shared.u64 t, %1; cvt.u32.u64 %0, t; }"
        : "=r"(a) : "l"(p));
    return a;
}
__device__ __forceinline__ uint32_t sw128(uint32_t off) {
    return off ^ ((off >> 3) & 0x70);
}
__device__ __forceinline__ void ldsm_x4(uint32_t (&r)[4], uint32_t addr) {
    asm volatile("ldmatrix.sync.aligned.m8n8.x4.shared.b16 {%0,%1,%2,%3}, [%4];"
        : "=r"(r[0]), "=r"(r[1]), "=r"(r[2]), "=r"(r[3]) : "r"(addr));
}
__device__ __forceinline__ void mma16816(float (&d)[4], const uint32_t (&a)[4],
                                         uint32_t b0, uint32_t b1) {
    asm volatile(
        "mma.sync.aligned.m16n8k16.row.col.f32.bf16.bf16.f32 "
        "{%0,%1,%2,%3}, {%4,%5,%6,%7}, {%8,%9}, {%0,%1,%2,%3};"
        : "+f"(d[0]), "+f"(d[1]), "+f"(d[2]), "+f"(d[3])
        : "r"(a[0]), "r"(a[1]), "r"(a[2]), "r"(a[3]), "r"(b0), "r"(b1));
}

// ---------------------------------------------------------------------------
// Split loader: 128 rows x 64 fp32 -> bf16 hi/lo SW128 tiles. 256 threads.
//   hi = trunc16(x) (exact top bits), lo = bf16_rn(x - hi)
// ---------------------------------------------------------------------------
__device__ __forceinline__ void split2(float a, float b, uint32_t& hi2, uint32_t& lo2) {
    uint32_t ua = __float_as_uint(a), ub = __float_as_uint(b);
    hi2 = __byte_perm(ua, ub, 0x7632);
    float ra = a - __uint_as_float(ua & 0xFFFF0000u);
    float rb = b - __uint_as_float(ub & 0xFFFF0000u);
    asm("cvt.rn.bf16x2.f32 %0, %1, %2;" : "=r"(lo2) : "f"(rb), "f"(ra));
}
__device__ __forceinline__ void load_split(char* dH, char* dL,
    const float* __restrict__ g, size_t rowStride, int tid)
{
#pragma unroll
    for (int t = 0; t < 4; t++) {
        int u = tid + t * 256;          // 1024 units of 8 floats
        int r = u >> 3, cu = u & 7;
        const float* p = g + (size_t)r * rowStride + cu * 8;
        float4 x0 = *(const float4*)p;
        float4 x1 = *(const float4*)(p + 4);
        uint32_t h0, l0, h1, l1, h2, l2, h3, l3;
        split2(x0.x, x0.y, h0, l0);
        split2(x0.z, x0.w, h1, l1);
        split2(x1.x, x1.y, h2, l2);
        split2(x1.z, x1.w, h3, l3);
        uint32_t sw = sw128((uint32_t)(r * 128 + cu * 16));
        *(uint4*)(dH + sw) = make_uint4(h0, h1, h2, h3);
        *(uint4*)(dL + sw) = make_uint4(l0, l1, l2, l3);
    }
}

// ---------------------------------------------------------------------------
// Shared mainloop: C[128 x 128] = A[128 x 512] * B[128 x 512]^T, 3-term bf16.
// 8 warps (4x2): warp tile 32(m) x 64(n); accum c[2][8][4] fp32.
// ---------------------------------------------------------------------------
__device__ __forceinline__ void gemm_tile(
    const float* __restrict__ Abase, size_t Astride,
    const float* __restrict__ Bbase, size_t Bstride,
    char* AH, char* AL, char* BH, char* BL,
    uint32_t uAH, uint32_t uAL, uint32_t uBH, uint32_t uBL,
    int tid, float (&c)[2][8][4])
{
    const int lane = tid & 31, wid = tid >> 5;
    const int m0 = (wid & 3) * 32, n0 = (wid >> 2) * 64;
    const uint32_t aRow = (uint32_t)(lane & 15);
    const uint32_t aKb  = (uint32_t)((lane >> 4) << 4);
    const uint32_t bRow = (uint32_t)((lane & 7) + ((lane >> 4) << 3));
    const uint32_t bKb  = (uint32_t)(((lane >> 3) & 1) << 4);

    for (int ch = 0; ch < 8; ch++) {
        __syncthreads();
        load_split(AH, AL, Abase + ch * 64, Astride, tid);
        load_split(BH, BL, Bbase + ch * 64, Bstride, tid);
        __syncthreads();
#pragma unroll
        for (int ks = 0; ks < 4; ks++) {
            const uint32_t kb0 = (uint32_t)(ks * 32);
            uint32_t ah[2][4], al[2][4];
#pragma unroll
            for (int mi = 0; mi < 2; mi++) {
                uint32_t off = sw128((uint32_t)(m0 + mi * 16 + aRow) * 128 + kb0 + aKb);
                ldsm_x4(ah[mi], uAH + off);
                ldsm_x4(al[mi], uAL + off);
            }
#pragma unroll
            for (int ng = 0; ng < 4; ng++) {
                uint32_t boff = sw128((uint32_t)(n0 + ng * 16 + bRow) * 128 + kb0 + bKb);
                uint32_t bh[4], bl[4];
                ldsm_x4(bh, uBH + boff);
                ldsm_x4(bl, uBL + boff);
#pragma unroll
                for (int mi = 0; mi < 2; mi++) {
                    mma16816(c[mi][2 * ng],     ah[mi], bh[0], bh[1]);
                    mma16816(c[mi][2 * ng],     ah[mi], bl[0], bl[1]);
                    mma16816(c[mi][2 * ng],     al[mi], bh[0], bh[1]);
                    mma16816(c[mi][2 * ng + 1], ah[mi], bh[2], bh[3]);
                    mma16816(c[mi][2 * ng + 1], ah[mi], bl[2], bl[3]);
                    mma16816(c[mi][2 * ng + 1], al[mi], bh[2], bh[3]);
                }
            }
        }
    }
}

// ===========================================================================
// Kernel 1: pred[l][m][c] = sum_k P[m][l][k]*W[c][k] + b[c]
//   grid = (ct=4, m=128, lblk=8), block = 256. Tile rows = 128 consecutive l.
// ===========================================================================
__global__ void __launch_bounds__(256, 2)
pred_tc(const float* __restrict__ P, const float* __restrict__ W,
        const float* __restrict__ bias)
{
    extern __shared__ char sm[];
    char *AH = sm, *AL = sm + 16384, *BH = sm + 32768, *BL = sm + 49152;
    const uint32_t u = smem_u32(sm);
    const int tid = threadIdx.x;
    const int c0 = blockIdx.x * 128, m = blockIdx.y, l0 = blockIdx.z * 128;

    float c[2][8][4];
#pragma unroll
    for (int i = 0; i < 2; i++)
#pragma unroll
        for (int j = 0; j < 8; j++)
#pragma unroll
            for (int k = 0; k < 4; k++) c[i][j][k] = 0.0f;

    gemm_tile(P + ((size_t)m * L_ + l0) * C_, C_,
              W + (size_t)c0 * C_, C_,
              AH, AL, BH, BL, u, u + 16384, u + 32768, u + 49152, tid, c);

    // Epilogue: + bias, store g_pred[l][m][c]
    const int lane = tid & 31, wid = tid >> 5;
    const int wm = wid & 3, wn = wid >> 2;
    const int tr = lane >> 2, tc = lane & 3;
#pragma unroll
    for (int mi = 0; mi < 2; mi++) {
        const int row = l0 + wm * 32 + mi * 16 + tr;
#pragma unroll
        for (int ni = 0; ni < 8; ni++) {
            const int col = c0 + wn * 64 + ni * 8 + 2 * tc;
            const float b0v = bias[col], b1v = bias[col + 1];
            float2 v0 = make_float2(c[mi][ni][0] + b0v, c[mi][ni][1] + b1v);
            float2 v1 = make_float2(c[mi][ni][2] + b0v, c[mi][ni][3] + b1v);
            *(float2*)(g_pred + ((size_t)row * N_ + m) * C_ + col)       = v0;
            *(float2*)(g_pred + ((size_t)(row + 8) * N_ + m) * C_ + col) = v1;
        }
    }
}

// ===========================================================================
// Kernel 2: l_neg[n][m] = sum_k T[n][l+step][k]*pred[l][m][k]
//   + fused NCE accuracy + scaled store to g_scr[lg][n][m]. grid = Ls.
// ===========================================================================
__global__ void __launch_bounds__(256, 2)
lneg_tc(const float* __restrict__ T, int step, int lofs, int cntIdx)
{
    extern __shared__ char sm[];
    char *AH = sm, *AL = sm + 16384, *BH = sm + 32768, *BL = sm + 49152;
    const uint32_t u = smem_u32(sm);
    const int tid = threadIdx.x;
    const int l = blockIdx.x;

    float c[2][8][4];
#pragma unroll
    for (int i = 0; i < 2; i++)
#pragma unroll
        for (int j = 0; j < 8; j++)
#pragma unroll
            for (int k = 0; k < 4; k++) c[i][j][k] = 0.0f;

    gemm_tile(T + (size_t)(l + step) * C_, (size_t)L_ * C_,
              g_pred + (size_t)l * (N_ * C_), C_,
              AH, AL, BH, BL, u, u + 16384, u + 32768, u + 49152, tid, c);

    // Dump accumulators to padded smem buffer s[n][m] (pitch 130)
    __syncthreads();
    float* s = (float*)sm;
    const int lane = tid & 31, wid = tid >> 5;
    const int wm = wid & 3, wn = wid >> 2;
    const int tr = lane >> 2, tc = lane & 3;
#pragma unroll
    for (int mi = 0; mi < 2; mi++) {
        const int row = wm * 32 + mi * 16 + tr;
#pragma unroll
        for (int ni = 0; ni < 8; ni++) {
            const int col = wn * 64 + ni * 8 + 2 * tc;
            *(float2*)&s[row * 130 + col]       = make_float2(c[mi][ni][0], c[mi][ni][1]);
            *(float2*)&s[(row + 8) * 130 + col] = make_float2(c[mi][ni][2], c[mi][ni][3]);
        }
    }
    __syncthreads();

    // NCE accuracy: row n true iff s[n][n] > s[n][m] for all m != n
    if (tid < 128) {
        const float pos = s[tid * 130 + tid];
        bool ok = true;
#pragma unroll 8
        for (int j = 0; j < 128; j++) ok &= (j == tid) || (pos > s[tid * 130 + j]);
        unsigned bal = __ballot_sync(0xFFFFFFFFu, ok);
        if ((tid & 31) == 0) atomicAdd(&g_count[cntIdx], (unsigned)__popc(bal));
    }

    // Coalesced scaled store: g_scr[lofs+l][n][m]
    float* dst = g_scr + (size_t)(lofs + l) * NM_;
#pragma unroll 8
    for (int idx = tid; idx < NM_; idx += 256)
        dst[idx] = s[(idx >> 7) * 130 + (idx & 127)] * INV_TEMP;
}

// ===========================================================================
// Transpose: out[nm][lg] = g_scr[lg][nm]  (32x32 smem tiles, both coalesced)
// ===========================================================================
__global__ void transpose_k(float* __restrict__ out)
{
    __shared__ float t[32][33];
    const int l0 = blockIdx.x * 32, p0 = blockIdx.y * 32;
    const int x = threadIdx.x, y = threadIdx.y;
#pragma unroll
    for (int i = y; i < 32; i += 8) {
        int lg = l0 + i;
        t[i][x] = (lg < LCAT_) ? g_scr[(size_t)lg * NM_ + (p0 + x)] : 0.0f;
    }
    __syncthreads();
#pragma unroll
    for (int i = y; i < 32; i += 8) {
        int lg = l0 + x;
        if (lg < LCAT_)
            out[(size_t)(p0 + i) * LCAT_ + lg] = t[x][i];
    }
}

// ---------------------------------------------------------------------------
// Init (y_trues + counters) and finalize (accs)
// ---------------------------------------------------------------------------
__global__ void init_kernel(float* __restrict__ out)
{
    if (blockIdx.x == 0 && threadIdx.x < 2) g_count[threadIdx.x] = 0u;
    const size_t idx = (size_t)blockIdx.x * 256 + threadIdx.x;
    if (idx < (size_t)N_ * LCAT_) {
        const size_t basep = (size_t)N_ * N_ * LCAT_;
        out[basep + idx] = (float)(idx / LCAT_);
    }
}
__global__ void fin_kernel(float* __restrict__ out)
{
    if (threadIdx.x == 0) {
        const size_t basep = (size_t)N_ * N_ * LCAT_ + (size_t)N_ * LCAT_;
        out[basep + 0] = (float)g_count[0] / (float)(N_ * 1023);
        out[basep + 1] = (float)g_count[1] / (float)(N_ * 1022);
    }
}

// ---------------------------------------------------------------------------
// Launch
// ---------------------------------------------------------------------------
extern "C" void kernel_launch(void* const* d_in, const int* in_sizes, int n_in,
                              void* d_out, int out_size)
{
    const float* ts = (const float*)d_in[0];
    const float* ps = (const float*)d_in[1];
    const float* W1 = (const float*)d_in[2];
    const float* b1 = (const float*)d_in[3];
    const float* W2 = (const float*)d_in[4];
    const float* b2 = (const float*)d_in[5];
    float* out = (float*)d_out;

    cudaFuncSetAttribute(pred_tc, cudaFuncAttributeMaxDynamicSharedMemorySize, SMEM_DYN);
    cudaFuncSetAttribute(lneg_tc, cudaFuncAttributeMaxDynamicSharedMemorySize, SMEM_DYN);

    init_kernel<<<1023, 256>>>(out);

    dim3 gp(4, 128, 8);
    pred_tc<<<gp, 256, SMEM_DYN>>>(ps, W1, b1);
    lneg_tc<<<1023, 256, SMEM_DYN>>>(ts, 1, 0, 0);

    pred_tc<<<gp, 256, SMEM_DYN>>>(ps, W2, b2);
    lneg_tc<<<1022, 256, SMEM_DYN>>>(ts, 2, 1023, 1);

    dim3 gt(64, 512), bt(32, 8);
    transpose_k<<<gt, bt>>>(out);
    fin_kernel<<<1, 32>>>(out);
}

// round 12
// speedup vs baseline: 2.1517x; 1.0152x over previous
#include <cuda_runtime.h>
#include <cuda_bf16.h>
#include <cstdint>

#define N_      128
#define L_      1024
#define C_      512
#define LCAT_   2045
#define INV_TEMP 14.285714285714285f
#define NM_     16384
#define SMEM_LNEG 66560     // lneg: 64KB tiles / 66.5KB epilogue buffer
#define SMEM_PRED 196608    // pred: 2 stages x 96KB

__device__ float g_pred[1024u * 128u * 512u];            // pred[l][m][c], fp32
__device__ float g_scr[(size_t)LCAT_ * NM_];             // logits scratch [lg][n][m]
__device__ __nv_bfloat16 g_psh[(size_t)N_ * L_ * C_];    // split(ps) hi
__device__ __nv_bfloat16 g_psl[(size_t)N_ * L_ * C_];    // split(ps) lo
__device__ __nv_bfloat16 g_wh[2][C_ * C_];               // split(W1/W2) hi
__device__ __nv_bfloat16 g_wl[2][C_ * C_];               // split(W1/W2) lo
__device__ unsigned int g_count[2];

// ---------------------------------------------------------------------------
// Helpers (base-target PTX only)
// ---------------------------------------------------------------------------
__device__ __forceinline__ uint32_t smem_u32(const void* p) {
    uint32_t a;
    asm("{ .reg .u64 t; cvta.to.shared.u64 t, %1; cvt.u32.u64 %0, t; }"
        : "=r"(a) : "l"(p));
    return a;
}
__device__ __forceinline__ uint32_t sw128(uint32_t off) {
    return off ^ ((off >> 3) & 0x70);
}
__device__ __forceinline__ void ldsm_x4(uint32_t (&r)[4], uint32_t addr) {
    asm volatile("ldmatrix.sync.aligned.m8n8.x4.shared.b16 {%0,%1,%2,%3}, [%4];"
        : "=r"(r[0]), "=r"(r[1]), "=r"(r[2]), "=r"(r[3]) : "r"(addr));
}
__device__ __forceinline__ void mma16816(float (&d)[4], const uint32_t (&a)[4],
                                         uint32_t b0, uint32_t b1) {
    asm volatile(
        "mma.sync.aligned.m16n8k16.row.col.f32.bf16.bf16.f32 "
        "{%0,%1,%2,%3}, {%4,%5,%6,%7}, {%8,%9}, {%0,%1,%2,%3};"
        : "+f"(d[0]), "+f"(d[1]), "+f"(d[2]), "+f"(d[3])
        : "r"(a[0]), "r"(a[1]), "r"(a[2]), "r"(a[3]), "r"(b0), "r"(b1));
}
__device__ __forceinline__ void cpasync16(uint32_t dst, const void* src) {
    asm volatile("cp.async.cg.shared.global [%0], [%1], 16;"
                 :: "r"(dst), "l"(src) : "memory");
}
#define CP_COMMIT() asm volatile("cp.async.commit_group;" ::: "memory")
#define CP_WAIT1()  asm volatile("cp.async.wait_group 1;" ::: "memory")
#define CP_WAIT0()  asm volatile("cp.async.wait_group 0;" ::: "memory")

// hi = trunc16(x) exact, lo = bf16_rn(x - hi)
__device__ __forceinline__ void split2(float a, float b, uint32_t& hi2, uint32_t& lo2) {
    uint32_t ua = __float_as_uint(a), ub = __float_as_uint(b);
    hi2 = __byte_perm(ua, ub, 0x7632);
    float ra = a - __uint_as_float(ua & 0xFFFF0000u);
    float rb = b - __uint_as_float(ub & 0xFFFF0000u);
    asm("cvt.rn.bf16x2.f32 %0, %1, %2;" : "=r"(lo2) : "f"(rb), "f"(ra));
}

// ===========================================================================
// Pre-split: fp32 -> bf16 hi/lo global arrays. n8 = count of 8-float units.
// ===========================================================================
__global__ void split_k(const float* __restrict__ src,
                        __nv_bfloat16* __restrict__ dh,
                        __nv_bfloat16* __restrict__ dl, size_t n8)
{
    size_t u = (size_t)blockIdx.x * blockDim.x + threadIdx.x;
    if (u >= n8) return;
    const float* p = src + u * 8;
    float4 x0 = *(const float4*)p;
    float4 x1 = *(const float4*)(p + 4);
    uint32_t h0, l0, h1, l1, h2, l2, h3, l3;
    split2(x0.x, x0.y, h0, l0);
    split2(x0.z, x0.w, h1, l1);
    split2(x1.x, x1.y, h2, l2);
    split2(x1.z, x1.w, h3, l3);
    *(uint4*)(dh + u * 8) = make_uint4(h0, h1, h2, h3);
    *(uint4*)(dl + u * 8) = make_uint4(l0, l1, l2, l3);
}

// ===========================================================================
// Kernel 1 (rewritten): pred[l][m][c] = sum_k P[m][l][k]*W[c][k] + b[c]
//   Block tile 256(l) x 128(c); 256 thr, 8 warps 4(m)x2(n), warp tile 64x64.
//   cp.async double-buffered, K-chunk 64. grid = (ct=4... actually 1 c-dim of
//   128 -> blockIdx.x in 0..3 covers c, y=m, z=lblk(4).
// ===========================================================================
__global__ void __launch_bounds__(256, 1)
pred_tc(const __nv_bfloat16* __restrict__ Ah_g, const __nv_bfloat16* __restrict__ Al_g,
        const __nv_bfloat16* __restrict__ Bh_g, const __nv_bfloat16* __restrict__ Bl_g,
        const float* __restrict__ bias)
{
    extern __shared__ char sm[];
    const uint32_t u0 = smem_u32(sm);
    const int tid = threadIdx.x;
    const int c0 = blockIdx.x * 128, m = blockIdx.y, l0 = blockIdx.z * 256;

    // Stage layout: base + s*98304 : AH 32KB | AL 32KB | BH 16KB | BL 16KB
    const __nv_bfloat16* Abase_h = Ah_g + ((size_t)m * L_ + l0) * C_;
    const __nv_bfloat16* Abase_l = Al_g + ((size_t)m * L_ + l0) * C_;
    const __nv_bfloat16* Bbase_h = Bh_g + (size_t)c0 * C_;
    const __nv_bfloat16* Bbase_l = Bl_g + (size_t)c0 * C_;

    // Per-thread cp.async mapping (A: 2048 chunks, B: 1024 chunks of 16B)
    const int ar = (tid + 0 * 256) >> 3;   // pattern: u>>3 with u=tid+t*256
    const int acu = tid & 7;               // (u&7) invariant across t (t*256 keeps low 3 bits)

    auto issue_chunk = [&](int ch, int stage) {
        const uint32_t sb = u0 + (uint32_t)stage * 98304u;
        const size_t kofs = (size_t)ch * 64;
#pragma unroll
        for (int t = 0; t < 8; t++) {
            int u = tid + t * 256;
            int r = u >> 3, cu = u & 7;
            size_t go = (size_t)r * C_ + kofs + cu * 8;
            uint32_t d = sw128((uint32_t)(r * 128 + cu * 16));
            cpasync16(sb + d, Abase_h + go);
            cpasync16(sb + 32768u + d, Abase_l + go);
        }
#pragma unroll
        for (int t = 0; t < 4; t++) {
            int u = tid + t * 256;
            int r = u >> 3, cu = u & 7;
            size_t go = (size_t)r * C_ + kofs + cu * 8;
            uint32_t d = sw128((uint32_t)(r * 128 + cu * 16));
            cpasync16(sb + 65536u + d, Bbase_h + go);
            cpasync16(sb + 81920u + d, Bbase_l + go);
        }
        CP_COMMIT();
    };
    (void)ar; (void)acu;

    float c[4][8][4];
#pragma unroll
    for (int i = 0; i < 4; i++)
#pragma unroll
        for (int j = 0; j < 8; j++)
#pragma unroll
            for (int k = 0; k < 4; k++) c[i][j][k] = 0.0f;

    const int lane = tid & 31, wid = tid >> 5;
    const int wm = wid & 3, wn = wid >> 2;           // warp grid 4(m) x 2(n)
    const int m0 = wm * 64, n0 = wn * 64;
    const uint32_t aRow = (uint32_t)(lane & 15);
    const uint32_t aKb  = (uint32_t)((lane >> 4) << 4);
    const uint32_t bRow = (uint32_t)((lane & 7) + ((lane >> 4) << 3));
    const uint32_t bKb  = (uint32_t)(((lane >> 3) & 1) << 4);

    issue_chunk(0, 0);
    issue_chunk(1, 1);

    for (int ch = 0; ch < 8; ch++) {
        if (ch < 7) CP_WAIT1(); else CP_WAIT0();
        __syncthreads();

        const uint32_t sb = u0 + (uint32_t)(ch & 1) * 98304u;
        const uint32_t uAH = sb, uAL = sb + 32768u;
        const uint32_t uBH = sb + 65536u, uBL = sb + 81920u;
#pragma unroll
        for (int ks = 0; ks < 4; ks++) {
            const uint32_t kb0 = (uint32_t)(ks * 32);
            uint32_t ah[4][4], al[4][4];
#pragma unroll
            for (int mi = 0; mi < 4; mi++) {
                uint32_t off = sw128((uint32_t)(m0 + mi * 16 + aRow) * 128 + kb0 + aKb);
                ldsm_x4(ah[mi], uAH + off);
                ldsm_x4(al[mi], uAL + off);
            }
#pragma unroll
            for (int ng = 0; ng < 4; ng++) {
                uint32_t boff = sw128((uint32_t)(n0 + ng * 16 + bRow) * 128 + kb0 + bKb);
                uint32_t bh[4], bl[4];
                ldsm_x4(bh, uBH + boff);
                ldsm_x4(bl, uBL + boff);
#pragma unroll
                for (int mi = 0; mi < 4; mi++) {
                    mma16816(c[mi][2 * ng],     ah[mi], bh[0], bh[1]);
                    mma16816(c[mi][2 * ng],     ah[mi], bl[0], bl[1]);
                    mma16816(c[mi][2 * ng],     al[mi], bh[0], bh[1]);
                    mma16816(c[mi][2 * ng + 1], ah[mi], bh[2], bh[3]);
                    mma16816(c[mi][2 * ng + 1], ah[mi], bl[2], bl[3]);
                    mma16816(c[mi][2 * ng + 1], al[mi], bh[2], bh[3]);
                }
            }
        }
        __syncthreads();
        if (ch + 2 < 8) issue_chunk(ch + 2, ch & 1);
    }

    // Epilogue: + bias, store fp32 g_pred[l][m][c]
    const int tr = lane >> 2, tc = lane & 3;
#pragma unroll
    for (int mi = 0; mi < 4; mi++) {
        const int lrow = l0 + m0 + mi * 16 + tr;
#pragma unroll
        for (int ni = 0; ni < 8; ni++) {
            const int col = c0 + n0 + ni * 8 + 2 * tc;
            const float b0v = bias[col], b1v = bias[col + 1];
            *(float2*)(g_pred + ((size_t)lrow * N_ + m) * C_ + col) =
                make_float2(c[mi][ni][0] + b0v, c[mi][ni][1] + b1v);
            *(float2*)(g_pred + ((size_t)(lrow + 8) * N_ + m) * C_ + col) =
                make_float2(c[mi][ni][2] + b0v, c[mi][ni][3] + b1v);
        }
    }
}

// ===========================================================================
// lneg (unchanged from R9, passing): fp32 inputs split inline, 32x64 warps
// ===========================================================================
__device__ __forceinline__ void load_split(char* dH, char* dL,
    const float* __restrict__ g, size_t rowStride, int tid)
{
#pragma unroll
    for (int t = 0; t < 4; t++) {
        int u = tid + t * 256;
        int r = u >> 3, cu = u & 7;
        const float* p = g + (size_t)r * rowStride + cu * 8;
        float4 x0 = *(const float4*)p;
        float4 x1 = *(const float4*)(p + 4);
        uint32_t h0, l0, h1, l1, h2, l2, h3, l3;
        split2(x0.x, x0.y, h0, l0);
        split2(x0.z, x0.w, h1, l1);
        split2(x1.x, x1.y, h2, l2);
        split2(x1.z, x1.w, h3, l3);
        uint32_t sw = sw128((uint32_t)(r * 128 + cu * 16));
        *(uint4*)(dH + sw) = make_uint4(h0, h1, h2, h3);
        *(uint4*)(dL + sw) = make_uint4(l0, l1, l2, l3);
    }
}

__global__ void __launch_bounds__(256, 2)
lneg_tc(const float* __restrict__ T, int step, int lofs, int cntIdx)
{
    extern __shared__ char sm[];
    char *AH = sm, *AL = sm + 16384, *BH = sm + 32768, *BL = sm + 49152;
    const uint32_t u = smem_u32(sm);
    const uint32_t uAH = u, uAL = u + 16384, uBH = u + 32768, uBL = u + 49152;
    const int tid = threadIdx.x;
    const int l = blockIdx.x;

    float c[2][8][4];
#pragma unroll
    for (int i = 0; i < 2; i++)
#pragma unroll
        for (int j = 0; j < 8; j++)
#pragma unroll
            for (int k = 0; k < 4; k++) c[i][j][k] = 0.0f;

    const float* Abase = T + (size_t)(l + step) * C_;
    const float* Bbase = g_pred + (size_t)l * (N_ * C_);

    const int lane = tid & 31, wid = tid >> 5;
    const int m0 = (wid & 3) * 32, n0 = (wid >> 2) * 64;
    const uint32_t aRow = (uint32_t)(lane & 15);
    const uint32_t aKb  = (uint32_t)((lane >> 4) << 4);
    const uint32_t bRow = (uint32_t)((lane & 7) + ((lane >> 4) << 3));
    const uint32_t bKb  = (uint32_t)(((lane >> 3) & 1) << 4);

    for (int ch = 0; ch < 8; ch++) {
        __syncthreads();
        load_split(AH, AL, Abase + ch * 64, (size_t)L_ * C_, tid);
        load_split(BH, BL, Bbase + ch * 64, C_, tid);
        __syncthreads();
#pragma unroll
        for (int ks = 0; ks < 4; ks++) {
            const uint32_t kb0 = (uint32_t)(ks * 32);
            uint32_t ah[2][4], al[2][4];
#pragma unroll
            for (int mi = 0; mi < 2; mi++) {
                uint32_t off = sw128((uint32_t)(m0 + mi * 16 + aRow) * 128 + kb0 + aKb);
                ldsm_x4(ah[mi], uAH + off);
                ldsm_x4(al[mi], uAL + off);
            }
#pragma unroll
            for (int ng = 0; ng < 4; ng++) {
                uint32_t boff = sw128((uint32_t)(n0 + ng * 16 + bRow) * 128 + kb0 + bKb);
                uint32_t bh[4], bl[4];
                ldsm_x4(bh, uBH + boff);
                ldsm_x4(bl, uBL + boff);
#pragma unroll
                for (int mi = 0; mi < 2; mi++) {
                    mma16816(c[mi][2 * ng],     ah[mi], bh[0], bh[1]);
                    mma16816(c[mi][2 * ng],     ah[mi], bl[0], bl[1]);
                    mma16816(c[mi][2 * ng],     al[mi], bh[0], bh[1]);
                    mma16816(c[mi][2 * ng + 1], ah[mi], bh[2], bh[3]);
                    mma16816(c[mi][2 * ng + 1], ah[mi], bl[2], bl[3]);
                    mma16816(c[mi][2 * ng + 1], al[mi], bh[2], bh[3]);
                }
            }
        }
    }

    __syncthreads();
    float* s = (float*)sm;
    const int wm = wid & 3, wn = wid >> 2;
    const int tr = lane >> 2, tc = lane & 3;
#pragma unroll
    for (int mi = 0; mi < 2; mi++) {
        const int row = wm * 32 + mi * 16 + tr;
#pragma unroll
        for (int ni = 0; ni < 8; ni++) {
            const int col = wn * 64 + ni * 8 + 2 * tc;
            *(float2*)&s[row * 130 + col]       = make_float2(c[mi][ni][0], c[mi][ni][1]);
            *(float2*)&s[(row + 8) * 130 + col] = make_float2(c[mi][ni][2], c[mi][ni][3]);
        }
    }
    __syncthreads();

    if (tid < 128) {
        const float pos = s[tid * 130 + tid];
        bool ok = true;
#pragma unroll 8
        for (int j = 0; j < 128; j++) ok &= (j == tid) || (pos > s[tid * 130 + j]);
        unsigned bal = __ballot_sync(0xFFFFFFFFu, ok);
        if ((tid & 31) == 0) atomicAdd(&g_count[cntIdx], (unsigned)__popc(bal));
    }

    float* dst = g_scr + (size_t)(lofs + l) * NM_;
#pragma unroll 8
    for (int idx = tid; idx < NM_; idx += 256)
        dst[idx] = s[(idx >> 7) * 130 + (idx & 127)] * INV_TEMP;
}

// ===========================================================================
// Transpose / init / finalize
// ===========================================================================
__global__ void transpose_k(float* __restrict__ out)
{
    __shared__ float t[32][33];
    const int l0 = blockIdx.x * 32, p0 = blockIdx.y * 32;
    const int x = threadIdx.x, y = threadIdx.y;
#pragma unroll
    for (int i = y; i < 32; i += 8) {
        int lg = l0 + i;
        t[i][x] = (lg < LCAT_) ? g_scr[(size_t)lg * NM_ + (p0 + x)] : 0.0f;
    }
    __syncthreads();
#pragma unroll
    for (int i = y; i < 32; i += 8) {
        int lg = l0 + x;
        if (lg < LCAT_)
            out[(size_t)(p0 + i) * LCAT_ + lg] = t[x][i];
    }
}
__global__ void init_kernel(float* __restrict__ out)
{
    if (blockIdx.x == 0 && threadIdx.x < 2) g_count[threadIdx.x] = 0u;
    const size_t idx = (size_t)blockIdx.x * 256 + threadIdx.x;
    if (idx < (size_t)N_ * LCAT_) {
        const size_t basep = (size_t)N_ * N_ * LCAT_;
        out[basep + idx] = (float)(idx / LCAT_);
    }
}
__global__ void fin_kernel(float* __restrict__ out)
{
    if (threadIdx.x == 0) {
        const size_t basep = (size_t)N_ * N_ * LCAT_ + (size_t)N_ * LCAT_;
        out[basep + 0] = (float)g_count[0] / (float)(N_ * 1023);
        out[basep + 1] = (float)g_count[1] / (float)(N_ * 1022);
    }
}

// ---------------------------------------------------------------------------
// Launch
// ---------------------------------------------------------------------------
extern "C" void kernel_launch(void* const* d_in, const int* in_sizes, int n_in,
                              void* d_out, int out_size)
{
    const float* ts = (const float*)d_in[0];
    const float* ps = (const float*)d_in[1];
    const float* W1 = (const float*)d_in[2];
    const float* b1 = (const float*)d_in[3];
    const float* W2 = (const float*)d_in[4];
    const float* b2 = (const float*)d_in[5];
    float* out = (float*)d_out;

    cudaFuncSetAttribute(pred_tc, cudaFuncAttributeMaxDynamicSharedMemorySize, SMEM_PRED);
    cudaFuncSetAttribute(lneg_tc, cudaFuncAttributeMaxDynamicSharedMemorySize, SMEM_LNEG);

    init_kernel<<<1023, 256>>>(out);

    // Pre-split inputs to bf16 hi/lo
    __nv_bfloat16 *psh, *psl, *w1h, *w1l, *w2h, *w2l;
    cudaGetSymbolAddress((void**)&psh, g_psh);
    cudaGetSymbolAddress((void**)&psl, g_psl);
    {
        void* p;
        cudaGetSymbolAddress(&p, g_wh); w1h = (__nv_bfloat16*)p; w2h = w1h + C_ * C_;
        cudaGetSymbolAddress(&p, g_wl); w1l = (__nv_bfloat16*)p; w2l = w1l + C_ * C_;
    }
    const size_t n8ps = (size_t)N_ * L_ * C_ / 8;
    split_k<<<(unsigned)((n8ps + 255) / 256), 256>>>(ps, psh, psl, n8ps);
    const size_t n8w = (size_t)C_ * C_ / 8;
    split_k<<<(unsigned)((n8w + 255) / 256), 256>>>(W1, w1h, w1l, n8w);
    split_k<<<(unsigned)((n8w + 255) / 256), 256>>>(W2, w2h, w2l, n8w);

    dim3 gp(4, 128, 4);   // c-tile, m, l-block(256)
    pred_tc<<<gp, 256, SMEM_PRED>>>(psh, psl, w1h, w1l, b1);
    lneg_tc<<<1023, 256, SMEM_LNEG>>>(ts, 1, 0, 0);

    pred_tc<<<gp, 256, SMEM_PRED>>>(psh, psl, w2h, w2l, b2);
    lneg_tc<<<1022, 256, SMEM_LNEG>>>(ts, 2, 1023, 1);

    dim3 gt(64, 512), bt(32, 8);
    transpose_k<<<gt, bt>>>(out);
    fin_kernel<<<1, 32>>>(out);
}

// round 14
// speedup vs baseline: 2.2051x; 1.0248x over previous
#include <cuda_runtime.h>
#include <cuda_bf16.h>
#include <cstdint>

#define N_      128
#define L_      1024
#define C_      512
#define LCAT_   2045
#define INV_TEMP 14.285714285714285f
#define NM_     16384
#define SMEM_FUSED 196608   // stages 2x64KB + predC 64KB

__device__ float g_scr[(size_t)LCAT_ * NM_];             // logits scratch [lg][n][m]
__device__ __nv_bfloat16 g_psh[(size_t)N_ * L_ * C_];
__device__ __nv_bfloat16 g_psl[(size_t)N_ * L_ * C_];
__device__ __nv_bfloat16 g_tsh[(size_t)N_ * L_ * C_];
__device__ __nv_bfloat16 g_tsl[(size_t)N_ * L_ * C_];
__device__ __nv_bfloat16 g_wh[2][C_ * C_];
__device__ __nv_bfloat16 g_wl[2][C_ * C_];
__device__ unsigned int g_count[2];

// ---------------------------------------------------------------------------
// Helpers (base-target PTX only)
// ---------------------------------------------------------------------------
__device__ __forceinline__ uint32_t smem_u32(const void* p) {
    uint32_t a;
    asm("{ .reg .u64 t; cvta.to.shared.u64 t, %1; cvt.u32.u64 %0, t; }"
        : "=r"(a) : "l"(p));
    return a;
}
__device__ __forceinline__ uint32_t sw128(uint32_t off) {
    return off ^ ((off >> 3) & 0x70);
}
__device__ __forceinline__ void ldsm_x4(uint32_t (&r)[4], uint32_t addr) {
    asm volatile("ldmatrix.sync.aligned.m8n8.x4.shared.b16 {%0,%1,%2,%3}, [%4];"
        : "=r"(r[0]), "=r"(r[1]), "=r"(r[2]), "=r"(r[3]) : "r"(addr));
}
__device__ __forceinline__ void mma16816(float (&d)[4], const uint32_t (&a)[4],
                                         uint32_t b0, uint32_t b1) {
    asm volatile(
        "mma.sync.aligned.m16n8k16.row.col.f32.bf16.bf16.f32 "
        "{%0,%1,%2,%3}, {%4,%5,%6,%7}, {%8,%9}, {%0,%1,%2,%3};"
        : "+f"(d[0]), "+f"(d[1]), "+f"(d[2]), "+f"(d[3])
        : "r"(a[0]), "r"(a[1]), "r"(a[2]), "r"(a[3]), "r"(b0), "r"(b1));
}
__device__ __forceinline__ void cpasync16(uint32_t dst, const void* src) {
    asm volatile("cp.async.cg.shared.global [%0], [%1], 16;"
                 :: "r"(dst), "l"(src) : "memory");
}
#define CP_COMMIT() asm volatile("cp.async.commit_group;" ::: "memory")
#define CP_WAIT1()  asm volatile("cp.async.wait_group 1;" ::: "memory")
#define CP_WAIT0()  asm volatile("cp.async.wait_group 0;" ::: "memory")

// hi = trunc16(x) exact, lo = bf16_rn(x - hi)
__device__ __forceinline__ void split2(float a, float b, uint32_t& hi2, uint32_t& lo2) {
    uint32_t ua = __float_as_uint(a), ub = __float_as_uint(b);
    hi2 = __byte_perm(ua, ub, 0x7632);
    float ra = a - __uint_as_float(ua & 0xFFFF0000u);
    float rb = b - __uint_as_float(ub & 0xFFFF0000u);
    asm("cvt.rn.bf16x2.f32 %0, %1, %2;" : "=r"(lo2) : "f"(rb), "f"(ra));
}

// ===========================================================================
// Pre-split: fp32 -> bf16 hi/lo
// ===========================================================================
__global__ void split_k(const float* __restrict__ src,
                        __nv_bfloat16* __restrict__ dh,
                        __nv_bfloat16* __restrict__ dl, size_t n8)
{
    size_t u = (size_t)blockIdx.x * blockDim.x + threadIdx.x;
    if (u >= n8) return;
    const float* p = src + u * 8;
    float4 x0 = *(const float4*)p;
    float4 x1 = *(const float4*)(p + 4);
    uint32_t h0, l0, h1, l1, h2, l2, h3, l3;
    split2(x0.x, x0.y, h0, l0);
    split2(x0.z, x0.w, h1, l1);
    split2(x1.x, x1.y, h2, l2);
    split2(x1.z, x1.w, h3, l3);
    *(uint4*)(dh + u * 8) = make_uint4(h0, h1, h2, h3);
    *(uint4*)(dl + u * 8) = make_uint4(l0, l1, l2, l3);
}

// ===========================================================================
// Fused kernel: per l, compute pred (4 c-chunks) and contract into lneg.
//   Block = 256 threads, 8 warps (4x2), warp tiles 32x64 in both GEMMs.
//   SMEM: [0,128K) two cp.async stages (AH|AL|BH|BL 16KB each);
//         [128K,192K) predC bf16 hi/lo, 2 sub-tiles (128m x 64c) each.
// ===========================================================================
__global__ void __launch_bounds__(256, 1)
fused_tc(const __nv_bfloat16* __restrict__ tsh, const __nv_bfloat16* __restrict__ tsl,
         const __nv_bfloat16* __restrict__ psh, const __nv_bfloat16* __restrict__ psl,
         const __nv_bfloat16* __restrict__ wh,  const __nv_bfloat16* __restrict__ wl,
         const float* __restrict__ bias, int step, int lofs, int cntIdx)
{
    extern __shared__ char sm[];
    __shared__ float sbias[C_];
    const uint32_t u0 = smem_u32(sm);
    const int tid = threadIdx.x;
    const int l = blockIdx.x;

    const int lane = tid & 31, wid = tid >> 5;
    const int wm = wid & 3, wn = wid >> 2;
    const int rowBlk = wm * 32, colBlk = wn * 64;
    const uint32_t aRow = (uint32_t)(lane & 15);
    const uint32_t aKb  = (uint32_t)((lane >> 4) << 4);
    const uint32_t bRow = (uint32_t)((lane & 7) + ((lane >> 4) << 3));
    const uint32_t bKb  = (uint32_t)(((lane >> 3) & 1) << 4);
    const int tr = lane >> 2, tc = lane & 3;

    sbias[tid] = bias[tid];
    sbias[tid + 256] = bias[tid + 256];

    const size_t rowStr = (size_t)L_ * C_;
    const uint32_t uPC = u0 + 131072u;           // predC hi base; lo at +32768

    float cL[2][8][4];
#pragma unroll
    for (int i = 0; i < 2; i++)
#pragma unroll
        for (int j = 0; j < 8; j++)
#pragma unroll
            for (int k = 0; k < 4; k++) cL[i][j][k] = 0.0f;

    for (int q = 0; q < 4; q++) {
        float cP[2][8][4];
#pragma unroll
        for (int i = 0; i < 2; i++)
#pragma unroll
            for (int j = 0; j < 8; j++)
#pragma unroll
                for (int k = 0; k < 4; k++) cP[i][j][k] = 0.0f;

        // ---- GEMM1: predC = P_l[128m x 512k] . W[q-chunk 128c x 512k]^T ----
        auto issueG1 = [&](int ch, int stage) {
            const uint32_t sb = u0 + (uint32_t)stage * 65536u;
#pragma unroll
            for (int t = 0; t < 4; t++) {
                int u = tid + t * 256;
                int r = u >> 3, cu = u & 7;
                uint32_t d = sw128((uint32_t)(r * 128 + cu * 16));
                size_t ga = (size_t)r * rowStr + (size_t)l * C_ + ch * 64 + cu * 8;
                cpasync16(sb + d, psh + ga);
                cpasync16(sb + 16384u + d, psl + ga);
                size_t gb = (size_t)(q * 128 + r) * C_ + ch * 64 + cu * 8;
                cpasync16(sb + 32768u + d, wh + gb);
                cpasync16(sb + 49152u + d, wl + gb);
            }
            CP_COMMIT();
        };
        issueG1(0, 0);
        issueG1(1, 1);

        for (int ch = 0; ch < 8; ch++) {
            if (ch < 7) CP_WAIT1(); else CP_WAIT0();
            __syncthreads();
            const uint32_t sb = u0 + (uint32_t)(ch & 1) * 65536u;
            const uint32_t uAH = sb, uAL = sb + 16384u;
            const uint32_t uBH = sb + 32768u, uBL = sb + 49152u;
#pragma unroll
            for (int ks = 0; ks < 4; ks++) {
                const uint32_t kb0 = (uint32_t)(ks * 32);
                uint32_t ah[2][4], al[2][4];
#pragma unroll
                for (int mi = 0; mi < 2; mi++) {
                    uint32_t off = sw128((uint32_t)(rowBlk + mi * 16 + aRow) * 128 + kb0 + aKb);
                    ldsm_x4(ah[mi], uAH + off);
                    ldsm_x4(al[mi], uAL + off);
                }
#pragma unroll
                for (int ng = 0; ng < 4; ng++) {
                    uint32_t boff = sw128((uint32_t)(colBlk + ng * 16 + bRow) * 128 + kb0 + bKb);
                    uint32_t bh[4], bl[4];
                    ldsm_x4(bh, uBH + boff);
                    ldsm_x4(bl, uBL + boff);
#pragma unroll
                    for (int mi = 0; mi < 2; mi++) {
                        mma16816(cP[mi][2 * ng],     ah[mi], bh[0], bh[1]);
                        mma16816(cP[mi][2 * ng],     ah[mi], bl[0], bl[1]);
                        mma16816(cP[mi][2 * ng],     al[mi], bh[0], bh[1]);
                        mma16816(cP[mi][2 * ng + 1], ah[mi], bh[2], bh[3]);
                        mma16816(cP[mi][2 * ng + 1], ah[mi], bl[2], bl[3]);
                        mma16816(cP[mi][2 * ng + 1], al[mi], bh[2], bh[3]);
                    }
                }
            }
            __syncthreads();
            if (ch + 2 < 8) issueG1(ch + 2, ch & 1);
        }

        // ---- Epilogue1: +bias, split to bf16 hi/lo, store predC smem tiles ----
        // predC sub-tile (sub = wn): [m=128][64c] SW128, hi at uPC+sub*16384, lo +32768
        {
            char* pc = sm + 131072;
#pragma unroll
            for (int mi = 0; mi < 2; mi++) {
                const int m0r = rowBlk + mi * 16 + tr;
#pragma unroll
                for (int ni = 0; ni < 8; ni++) {
                    const int cin = ni * 8 + 2 * tc;               // col within 64-sub
                    const float b0v = sbias[q * 128 + colBlk + cin];
                    const float b1v = sbias[q * 128 + colBlk + cin + 1];
                    uint32_t h2a, l2a, h2b, l2b;
                    split2(cP[mi][ni][0] + b0v, cP[mi][ni][1] + b1v, h2a, l2a);
                    split2(cP[mi][ni][2] + b0v, cP[mi][ni][3] + b1v, h2b, l2b);
                    uint32_t o0 = sw128((uint32_t)(m0r * 128 + cin * 2));
                    uint32_t o1 = sw128((uint32_t)((m0r + 8) * 128 + cin * 2));
                    const int sb16 = wn * 16384;
                    *(uint32_t*)(pc + sb16 + o0)           = h2a;
                    *(uint32_t*)(pc + sb16 + 32768 + o0)   = l2a;
                    *(uint32_t*)(pc + sb16 + o1)           = h2b;
                    *(uint32_t*)(pc + sb16 + 32768 + o1)   = l2b;
                }
            }
        }
        __syncthreads();   // predC visible; stage buffers free

        // ---- Load T chunk (A2): rows n, k = c in [q*128, q*128+128) ----
#pragma unroll
        for (int sub = 0; sub < 2; sub++) {
            const uint32_t sb = u0 + (uint32_t)sub * 65536u;
#pragma unroll
            for (int t = 0; t < 4; t++) {
                int u = tid + t * 256;
                int r = u >> 3, cu = u & 7;
                uint32_t d = sw128((uint32_t)(r * 128 + cu * 16));
                size_t ga = (size_t)r * rowStr + (size_t)(l + step) * C_
                          + q * 128 + sub * 64 + cu * 8;
                cpasync16(sb + d, tsh + ga);
                cpasync16(sb + 16384u + d, tsl + ga);
            }
        }
        CP_COMMIT();
        CP_WAIT0();
        __syncthreads();

        // ---- GEMM2: cL += T2[128n x 128c] . predC[128m x 128c]^T ----
#pragma unroll
        for (int ks = 0; ks < 8; ks++) {
            const int sub = ks >> 2;
            const uint32_t kb0 = (uint32_t)((ks & 3) * 32);
            const uint32_t uA = u0 + (uint32_t)sub * 65536u;
            const uint32_t uB = uPC + (uint32_t)sub * 16384u;
            uint32_t ah[2][4], al[2][4];
#pragma unroll
            for (int mi = 0; mi < 2; mi++) {
                uint32_t off = sw128((uint32_t)(rowBlk + mi * 16 + aRow) * 128 + kb0 + aKb);
                ldsm_x4(ah[mi], uA + off);
                ldsm_x4(al[mi], uA + 16384u + off);
            }
#pragma unroll
            for (int ng = 0; ng < 4; ng++) {
                uint32_t boff = sw128((uint32_t)(colBlk + ng * 16 + bRow) * 128 + kb0 + bKb);
                uint32_t bh[4], bl[4];
                ldsm_x4(bh, uB + boff);
                ldsm_x4(bl, uB + 32768u + boff);
#pragma unroll
                for (int mi = 0; mi < 2; mi++) {
                    mma16816(cL[mi][2 * ng],     ah[mi], bh[0], bh[1]);
                    mma16816(cL[mi][2 * ng],     ah[mi], bl[0], bl[1]);
                    mma16816(cL[mi][2 * ng],     al[mi], bh[0], bh[1]);
                    mma16816(cL[mi][2 * ng + 1], ah[mi], bh[2], bh[3]);
                    mma16816(cL[mi][2 * ng + 1], ah[mi], bl[2], bl[3]);
                    mma16816(cL[mi][2 * ng + 1], al[mi], bh[2], bh[3]);
                }
            }
        }
        __syncthreads();   // done with stages + predC before next q
    }

    // ---- Final epilogue: dump cL, NCE accuracy, scaled scratch store ----
    float* s = (float*)sm;
#pragma unroll
    for (int mi = 0; mi < 2; mi++) {
        const int row = rowBlk + mi * 16 + tr;
#pragma unroll
        for (int ni = 0; ni < 8; ni++) {
            const int col = colBlk + ni * 8 + 2 * tc;
            *(float2*)&s[row * 130 + col]       = make_float2(cL[mi][ni][0], cL[mi][ni][1]);
            *(float2*)&s[(row + 8) * 130 + col] = make_float2(cL[mi][ni][2], cL[mi][ni][3]);
        }
    }
    __syncthreads();

    if (tid < 128) {
        const float pos = s[tid * 130 + tid];
        bool ok = true;
#pragma unroll 8
        for (int j = 0; j < 128; j++) ok &= (j == tid) || (pos > s[tid * 130 + j]);
        unsigned bal = __ballot_sync(0xFFFFFFFFu, ok);
        if ((tid & 31) == 0) atomicAdd(&g_count[cntIdx], (unsigned)__popc(bal));
    }

    float* dst = g_scr + (size_t)(lofs + l) * NM_;
#pragma unroll 8
    for (int idx = tid; idx < NM_; idx += 256)
        dst[idx] = s[(idx >> 7) * 130 + (idx & 127)] * INV_TEMP;
}

// ===========================================================================
// Transpose / init / finalize
// ===========================================================================
__global__ void transpose_k(float* __restrict__ out)
{
    __shared__ float t[32][33];
    const int l0 = blockIdx.x * 32, p0 = blockIdx.y * 32;
    const int x = threadIdx.x, y = threadIdx.y;
#pragma unroll
    for (int i = y; i < 32; i += 8) {
        int lg = l0 + i;
        t[i][x] = (lg < LCAT_) ? g_scr[(size_t)lg * NM_ + (p0 + x)] : 0.0f;
    }
    __syncthreads();
#pragma unroll
    for (int i = y; i < 32; i += 8) {
        int lg = l0 + x;
        if (lg < LCAT_)
            out[(size_t)(p0 + i) * LCAT_ + lg] = t[x][i];
    }
}
__global__ void init_kernel(float* __restrict__ out)
{
    if (blockIdx.x == 0 && threadIdx.x < 2) g_count[threadIdx.x] = 0u;
    const size_t idx = (size_t)blockIdx.x * 256 + threadIdx.x;
    if (idx < (size_t)N_ * LCAT_) {
        const size_t basep = (size_t)N_ * N_ * LCAT_;
        out[basep + idx] = (float)(idx / LCAT_);
    }
}
__global__ void fin_kernel(float* __restrict__ out)
{
    if (threadIdx.x == 0) {
        const size_t basep = (size_t)N_ * N_ * LCAT_ + (size_t)N_ * LCAT_;
        out[basep + 0] = (float)g_count[0] / (float)(N_ * 1023);
        out[basep + 1] = (float)g_count[1] / (float)(N_ * 1022);
    }
}

// ---------------------------------------------------------------------------
// Launch
// ---------------------------------------------------------------------------
extern "C" void kernel_launch(void* const* d_in, const int* in_sizes, int n_in,
                              void* d_out, int out_size)
{
    const float* ts = (const float*)d_in[0];
    const float* ps = (const float*)d_in[1];
    const float* W1 = (const float*)d_in[2];
    const float* b1 = (const float*)d_in[3];
    const float* W2 = (const float*)d_in[4];
    const float* b2 = (const float*)d_in[5];
    float* out = (float*)d_out;

    cudaFuncSetAttribute(fused_tc, cudaFuncAttributeMaxDynamicSharedMemorySize, SMEM_FUSED);

    init_kernel<<<1023, 256>>>(out);

    __nv_bfloat16 *psh, *psl, *tsh, *tsl, *w1h, *w1l, *w2h, *w2l;
    cudaGetSymbolAddress((void**)&psh, g_psh);
    cudaGetSymbolAddress((void**)&psl, g_psl);
    cudaGetSymbolAddress((void**)&tsh, g_tsh);
    cudaGetSymbolAddress((void**)&tsl, g_tsl);
    {
        void* p;
        cudaGetSymbolAddress(&p, g_wh); w1h = (__nv_bfloat16*)p; w2h = w1h + C_ * C_;
        cudaGetSymbolAddress(&p, g_wl); w1l = (__nv_bfloat16*)p; w2l = w1l + C_ * C_;
    }
    const size_t n8 = (size_t)N_ * L_ * C_ / 8;
    split_k<<<(unsigned)((n8 + 255) / 256), 256>>>(ps, psh, psl, n8);
    split_k<<<(unsigned)((n8 + 255) / 256), 256>>>(ts, tsh, tsl, n8);
    const size_t n8w = (size_t)C_ * C_ / 8;
    split_k<<<(unsigned)((n8w + 255) / 256), 256>>>(W1, w1h, w1l, n8w);
    split_k<<<(unsigned)((n8w + 255) / 256), 256>>>(W2, w2h, w2l, n8w);

    fused_tc<<<1023, 256, SMEM_FUSED>>>(tsh, tsl, psh, psl, w1h, w1l, b1, 1, 0, 0);
    fused_tc<<<1022, 256, SMEM_FUSED>>>(tsh, tsl, psh, psl, w2h, w2l, b2, 2, 1023, 1);

    dim3 gt(64, 512), bt(32, 8);
    transpose_k<<<gt, bt>>>(out);
    fin_kernel<<<1, 32>>>(out);
}

// round 15
// speedup vs baseline: 2.9747x; 1.3490x over previous
#include <cuda_runtime.h>
#include <cuda_fp16.h>
#include <cstdint>

#define N_      128
#define L_      1024
#define C_      512
#define LCAT_   2045
#define INV_TEMP 14.285714285714285f
#define NM_     16384
#define SMEM_FUSED 196608   // 2 stages x 48KB + predC 32KB + T 64KB

__device__ float g_scr[(size_t)LCAT_ * NM_];   // logits scratch [lg][n][m]
__device__ __half g_psh[(size_t)N_ * L_ * C_];
__device__ __half g_psl[(size_t)N_ * L_ * C_];
__device__ __half g_tsh[(size_t)N_ * L_ * C_];
__device__ __half g_tsl[(size_t)N_ * L_ * C_];
__device__ __half g_wh[2][C_ * C_];            // W rounded to fp16 (no split)
__device__ unsigned int g_count[2];

// ---------------------------------------------------------------------------
// Helpers (base-target PTX only)
// ---------------------------------------------------------------------------
__device__ __forceinline__ uint32_t smem_u32(const void* p) {
    uint32_t a;
    asm("{ .reg .u64 t; cvta.to.shared.u64 t, %1; cvt.u32.u64 %0, t; }"
        : "=r"(a) : "l"(p));
    return a;
}
__device__ __forceinline__ uint32_t sw128(uint32_t off) {
    return off ^ ((off >> 3) & 0x70);
}
__device__ __forceinline__ void ldsm_x4(uint32_t (&r)[4], uint32_t addr) {
    asm volatile("ldmatrix.sync.aligned.m8n8.x4.shared.b16 {%0,%1,%2,%3}, [%4];"
        : "=r"(r[0]), "=r"(r[1]), "=r"(r[2]), "=r"(r[3]) : "r"(addr));
}
__device__ __forceinline__ void mma16816(float (&d)[4], const uint32_t (&a)[4],
                                         uint32_t b0, uint32_t b1) {
    asm volatile(
        "mma.sync.aligned.m16n8k16.row.col.f32.f16.f16.f32 "
        "{%0,%1,%2,%3}, {%4,%5,%6,%7}, {%8,%9}, {%0,%1,%2,%3};"
        : "+f"(d[0]), "+f"(d[1]), "+f"(d[2]), "+f"(d[3])
        : "r"(a[0]), "r"(a[1]), "r"(a[2]), "r"(a[3]), "r"(b0), "r"(b1));
}
__device__ __forceinline__ void cpasync16(uint32_t dst, const void* src) {
    asm volatile("cp.async.cg.shared.global [%0], [%1], 16;"
                 :: "r"(dst), "l"(src) : "memory");
}
#define CP_COMMIT() asm volatile("cp.async.commit_group;" ::: "memory")
#define CP_WAIT1()  asm volatile("cp.async.wait_group 1;" ::: "memory")
#define CP_WAIT0()  asm volatile("cp.async.wait_group 0;" ::: "memory")

// fp16 pair split: h = rn(x), l = rn(x - h)
__device__ __forceinline__ void splitp(float a, float b, uint32_t& h2, uint32_t& l2) {
    __half2 h = __floats2half2_rn(a, b);
    float2 hf = __half22float2(h);
    __half2 l = __floats2half2_rn(a - hf.x, b - hf.y);
    h2 = *reinterpret_cast<uint32_t*>(&h);
    l2 = *reinterpret_cast<uint32_t*>(&l);
}

// ===========================================================================
// Pre-split kernels
// ===========================================================================
__global__ void split_pair_k(const float* __restrict__ src,
                             __half* __restrict__ dh, __half* __restrict__ dl,
                             size_t n8)
{
    size_t u = (size_t)blockIdx.x * blockDim.x + threadIdx.x;
    if (u >= n8) return;
    const float* p = src + u * 8;
    float4 x0 = *(const float4*)p;
    float4 x1 = *(const float4*)(p + 4);
    uint32_t h0, l0, h1, l1, h2, l2, h3, l3;
    splitp(x0.x, x0.y, h0, l0);
    splitp(x0.z, x0.w, h1, l1);
    splitp(x1.x, x1.y, h2, l2);
    splitp(x1.z, x1.w, h3, l3);
    *(uint4*)(dh + u * 8) = make_uint4(h0, h1, h2, h3);
    *(uint4*)(dl + u * 8) = make_uint4(l0, l1, l2, l3);
}
__global__ void round_k(const float* __restrict__ src,
                        __half* __restrict__ dh, size_t n8)
{
    size_t u = (size_t)blockIdx.x * blockDim.x + threadIdx.x;
    if (u >= n8) return;
    const float* p = src + u * 8;
    float4 x0 = *(const float4*)p;
    float4 x1 = *(const float4*)(p + 4);
    __half2 a = __floats2half2_rn(x0.x, x0.y);
    __half2 b = __floats2half2_rn(x0.z, x0.w);
    __half2 c = __floats2half2_rn(x1.x, x1.y);
    __half2 d = __floats2half2_rn(x1.z, x1.w);
    *(uint4*)(dh + u * 8) = make_uint4(
        *reinterpret_cast<uint32_t*>(&a), *reinterpret_cast<uint32_t*>(&b),
        *reinterpret_cast<uint32_t*>(&c), *reinterpret_cast<uint32_t*>(&d));
}

// ===========================================================================
// Fused kernel. SMEM map (dynamic):
//   stage s (s=0,1) @ s*49152 : AH 16K | AL 16K | BH 16K
//   predC  @ 98304 : 2 c-sub-tiles (128m x 64c fp16) of 16K         (32K)
//   Th     @ 131072: 2 c-sub-tiles of 16K; Tl @ 163840 likewise     (64K)
// ===========================================================================
__global__ void __launch_bounds__(256, 1)
fused_tc(const __half* __restrict__ tsh, const __half* __restrict__ tsl,
         const __half* __restrict__ psh, const __half* __restrict__ psl,
         const __half* __restrict__ wh,
         const float* __restrict__ bias, int step, int lofs, int cntIdx)
{
    extern __shared__ char sm[];
    __shared__ float sbias[C_];
    const uint32_t u0 = smem_u32(sm);
    const int tid = threadIdx.x;
    const int l = blockIdx.x;

    const int lane = tid & 31, wid = tid >> 5;
    const int wm = wid & 3, wn = wid >> 2;
    const int rowBlk = wm * 32, colBlk = wn * 64;
    const uint32_t aRow = (uint32_t)(lane & 15);
    const uint32_t aKb  = (uint32_t)((lane >> 4) << 4);
    const uint32_t bRow = (uint32_t)((lane & 7) + ((lane >> 4) << 3));
    const uint32_t bKb  = (uint32_t)(((lane >> 3) & 1) << 4);
    const int tr = lane >> 2, tc = lane & 3;

    sbias[tid] = bias[tid];
    sbias[tid + 256] = bias[tid + 256];

    const size_t rowStr = (size_t)L_ * C_;

    // Issue one GEMM1 K-chunk (A=P rows m, B=W q-chunk rows c); optionally T.
    auto issueG1 = [&](int qq, int ch, int stage, bool withT) {
        const uint32_t sb = u0 + (uint32_t)stage * 49152u;
#pragma unroll
        for (int t = 0; t < 4; t++) {
            int u = tid + t * 256;
            int r = u >> 3, cu = u & 7;
            uint32_t d = sw128((uint32_t)(r * 128 + cu * 16));
            size_t ga = (size_t)r * rowStr + (size_t)l * C_ + ch * 64 + cu * 8;
            cpasync16(sb + d, psh + ga);
            cpasync16(sb + 16384u + d, psl + ga);
            size_t gb = (size_t)(qq * 128 + r) * C_ + ch * 64 + cu * 8;
            cpasync16(sb + 32768u + d, wh + gb);
        }
        if (withT) {
#pragma unroll
            for (int s = 0; s < 2; s++) {
#pragma unroll
                for (int t = 0; t < 4; t++) {
                    int u = tid + t * 256;
                    int r = u >> 3, cu = u & 7;
                    uint32_t d = sw128((uint32_t)(r * 128 + cu * 16));
                    size_t ga = (size_t)r * rowStr + (size_t)(l + step) * C_
                              + qq * 128 + s * 64 + cu * 8;
                    cpasync16(u0 + 131072u + (uint32_t)s * 16384u + d, tsh + ga);
                    cpasync16(u0 + 163840u + (uint32_t)s * 16384u + d, tsl + ga);
                }
            }
        }
        CP_COMMIT();
    };

    float cL[2][8][4];
#pragma unroll
    for (int i = 0; i < 2; i++)
#pragma unroll
        for (int j = 0; j < 8; j++)
#pragma unroll
            for (int k = 0; k < 4; k++) cL[i][j][k] = 0.0f;

    issueG1(0, 0, 0, false);
    issueG1(0, 1, 1, true);

    for (int q = 0; q < 4; q++) {
        float cP[2][8][4];
#pragma unroll
        for (int i = 0; i < 2; i++)
#pragma unroll
            for (int j = 0; j < 8; j++)
#pragma unroll
                for (int k = 0; k < 4; k++) cP[i][j][k] = 0.0f;

        // ---- GEMM1: predC = P_l[128m x 512k] . W_q[128c x 512k]^T ----
        for (int ch = 0; ch < 8; ch++) {
            if (ch < 7) CP_WAIT1(); else CP_WAIT0();
            __syncthreads();
            const uint32_t sb = u0 + (uint32_t)(ch & 1) * 49152u;
            const uint32_t uAH = sb, uAL = sb + 16384u, uBH = sb + 32768u;
#pragma unroll
            for (int ks = 0; ks < 4; ks++) {
                const uint32_t kb0 = (uint32_t)(ks * 32);
                uint32_t ah[2][4], al[2][4];
#pragma unroll
                for (int mi = 0; mi < 2; mi++) {
                    uint32_t off = sw128((uint32_t)(rowBlk + mi * 16 + aRow) * 128 + kb0 + aKb);
                    ldsm_x4(ah[mi], uAH + off);
                    ldsm_x4(al[mi], uAL + off);
                }
#pragma unroll
                for (int ng = 0; ng < 4; ng++) {
                    uint32_t boff = sw128((uint32_t)(colBlk + ng * 16 + bRow) * 128 + kb0 + bKb);
                    uint32_t bh[4];
                    ldsm_x4(bh, uBH + boff);
#pragma unroll
                    for (int mi = 0; mi < 2; mi++) {
                        mma16816(cP[mi][2 * ng],     ah[mi], bh[0], bh[1]);
                        mma16816(cP[mi][2 * ng],     al[mi], bh[0], bh[1]);
                        mma16816(cP[mi][2 * ng + 1], ah[mi], bh[2], bh[3]);
                        mma16816(cP[mi][2 * ng + 1], al[mi], bh[2], bh[3]);
                    }
                }
            }
            __syncthreads();
            if (ch + 2 < 8) issueG1(q, ch + 2, ch & 1, false);
        }

        // ---- Epilogue1: +bias -> fp16 predC sub-tiles (sub = wn) ----
        {
            char* pc = sm + 98304;
            const int sb16 = wn * 16384;
#pragma unroll
            for (int mi = 0; mi < 2; mi++) {
                const int m0r = rowBlk + mi * 16 + tr;
#pragma unroll
                for (int ni = 0; ni < 8; ni++) {
                    const int cin = ni * 8 + 2 * tc;
                    const float b0v = sbias[q * 128 + colBlk + cin];
                    const float b1v = sbias[q * 128 + colBlk + cin + 1];
                    __half2 ha = __floats2half2_rn(cP[mi][ni][0] + b0v, cP[mi][ni][1] + b1v);
                    __half2 hb = __floats2half2_rn(cP[mi][ni][2] + b0v, cP[mi][ni][3] + b1v);
                    uint32_t o0 = sw128((uint32_t)(m0r * 128 + cin * 2));
                    uint32_t o1 = sw128((uint32_t)((m0r + 8) * 128 + cin * 2));
                    *(uint32_t*)(pc + sb16 + o0) = *reinterpret_cast<uint32_t*>(&ha);
                    *(uint32_t*)(pc + sb16 + o1) = *reinterpret_cast<uint32_t*>(&hb);
                }
            }
        }
        __syncthreads();
        if (q < 3) issueG1(q + 1, 0, 0, false);   // overlap next-q load with GEMM2

        // ---- GEMM2: cL += T_q[128n x 128c] . predC[128m x 128c]^T ----
#pragma unroll
        for (int ks = 0; ks < 8; ks++) {
            const int sub = ks >> 2;
            const uint32_t kb0 = (uint32_t)((ks & 3) * 32);
            const uint32_t uTh = u0 + 131072u + (uint32_t)sub * 16384u;
            const uint32_t uTl = u0 + 163840u + (uint32_t)sub * 16384u;
            const uint32_t uB  = u0 + 98304u  + (uint32_t)sub * 16384u;
            uint32_t ah[2][4], al[2][4];
#pragma unroll
            for (int mi = 0; mi < 2; mi++) {
                uint32_t off = sw128((uint32_t)(rowBlk + mi * 16 + aRow) * 128 + kb0 + aKb);
                ldsm_x4(ah[mi], uTh + off);
                ldsm_x4(al[mi], uTl + off);
            }
#pragma unroll
            for (int ng = 0; ng < 4; ng++) {
                uint32_t boff = sw128((uint32_t)(colBlk + ng * 16 + bRow) * 128 + kb0 + bKb);
                uint32_t bh[4];
                ldsm_x4(bh, uB + boff);
#pragma unroll
                for (int mi = 0; mi < 2; mi++) {
                    mma16816(cL[mi][2 * ng],     ah[mi], bh[0], bh[1]);
                    mma16816(cL[mi][2 * ng],     al[mi], bh[0], bh[1]);
                    mma16816(cL[mi][2 * ng + 1], ah[mi], bh[2], bh[3]);
                    mma16816(cL[mi][2 * ng + 1], al[mi], bh[2], bh[3]);
                }
            }
        }
        __syncthreads();
        if (q < 3) issueG1(q + 1, 1, 1, true);    // T region free now
    }

    // ---- Final epilogue: dump cL, NCE accuracy, scaled scratch store ----
    float* s = (float*)sm;
#pragma unroll
    for (int mi = 0; mi < 2; mi++) {
        const int row = rowBlk + mi * 16 + tr;
#pragma unroll
        for (int ni = 0; ni < 8; ni++) {
            const int col = colBlk + ni * 8 + 2 * tc;
            *(float2*)&s[row * 130 + col]       = make_float2(cL[mi][ni][0], cL[mi][ni][1]);
            *(float2*)&s[(row + 8) * 130 + col] = make_float2(cL[mi][ni][2], cL[mi][ni][3]);
        }
    }
    __syncthreads();

    if (tid < 128) {
        const float pos = s[tid * 130 + tid];
        bool ok = true;
#pragma unroll 8
        for (int j = 0; j < 128; j++) ok &= (j == tid) || (pos > s[tid * 130 + j]);
        unsigned bal = __ballot_sync(0xFFFFFFFFu, ok);
        if ((tid & 31) == 0) atomicAdd(&g_count[cntIdx], (unsigned)__popc(bal));
    }

    float* dst = g_scr + (size_t)(lofs + l) * NM_;
#pragma unroll 8
    for (int idx = tid; idx < NM_; idx += 256)
        dst[idx] = s[(idx >> 7) * 130 + (idx & 127)] * INV_TEMP;
}

// ===========================================================================
// Transpose / init / finalize
// ===========================================================================
__global__ void transpose_k(float* __restrict__ out)
{
    __shared__ float t[32][33];
    const int l0 = blockIdx.x * 32, p0 = blockIdx.y * 32;
    const int x = threadIdx.x, y = threadIdx.y;
#pragma unroll
    for (int i = y; i < 32; i += 8) {
        int lg = l0 + i;
        t[i][x] = (lg < LCAT_) ? g_scr[(size_t)lg * NM_ + (p0 + x)] : 0.0f;
    }
    __syncthreads();
#pragma unroll
    for (int i = y; i < 32; i += 8) {
        int lg = l0 + x;
        if (lg < LCAT_)
            out[(size_t)(p0 + i) * LCAT_ + lg] = t[x][i];
    }
}
__global__ void init_kernel(float* __restrict__ out)
{
    if (blockIdx.x == 0 && threadIdx.x < 2) g_count[threadIdx.x] = 0u;
    const size_t idx = (size_t)blockIdx.x * 256 + threadIdx.x;
    if (idx < (size_t)N_ * LCAT_) {
        const size_t basep = (size_t)N_ * N_ * LCAT_;
        out[basep + idx] = (float)(idx / LCAT_);
    }
}
__global__ void fin_kernel(float* __restrict__ out)
{
    if (threadIdx.x == 0) {
        const size_t basep = (size_t)N_ * N_ * LCAT_ + (size_t)N_ * LCAT_;
        out[basep + 0] = (float)g_count[0] / (float)(N_ * 1023);
        out[basep + 1] = (float)g_count[1] / (float)(N_ * 1022);
    }
}

// ---------------------------------------------------------------------------
// Launch
// ---------------------------------------------------------------------------
extern "C" void kernel_launch(void* const* d_in, const int* in_sizes, int n_in,
                              void* d_out, int out_size)
{
    const float* ts = (const float*)d_in[0];
    const float* ps = (const float*)d_in[1];
    const float* W1 = (const float*)d_in[2];
    const float* b1 = (const float*)d_in[3];
    const float* W2 = (const float*)d_in[4];
    const float* b2 = (const float*)d_in[5];
    float* out = (float*)d_out;

    cudaFuncSetAttribute(fused_tc, cudaFuncAttributeMaxDynamicSharedMemorySize, SMEM_FUSED);

    init_kernel<<<1023, 256>>>(out);

    __half *psh, *psl, *tsh, *tsl, *w1h, *w2h;
    cudaGetSymbolAddress((void**)&psh, g_psh);
    cudaGetSymbolAddress((void**)&psl, g_psl);
    cudaGetSymbolAddress((void**)&tsh, g_tsh);
    cudaGetSymbolAddress((void**)&tsl, g_tsl);
    {
        void* p;
        cudaGetSymbolAddress(&p, g_wh);
        w1h = (__half*)p;
        w2h = w1h + C_ * C_;
    }
    const size_t n8 = (size_t)N_ * L_ * C_ / 8;
    split_pair_k<<<(unsigned)((n8 + 255) / 256), 256>>>(ps, psh, psl, n8);
    split_pair_k<<<(unsigned)((n8 + 255) / 256), 256>>>(ts, tsh, tsl, n8);
    const size_t n8w = (size_t)C_ * C_ / 8;
    round_k<<<(unsigned)((n8w + 255) / 256), 256>>>(W1, w1h, n8w);
    round_k<<<(unsigned)((n8w + 255) / 256), 256>>>(W2, w2h, n8w);

    fused_tc<<<1023, 256, SMEM_FUSED>>>(tsh, tsl, psh, psl, w1h, b1, 1, 0, 0);
    fused_tc<<<1022, 256, SMEM_FUSED>>>(tsh, tsl, psh, psl, w2h, b2, 2, 1023, 1);

    dim3 gt(64, 512), bt(32, 8);
    transpose_k<<<gt, bt>>>(out);
    fin_kernel<<<1, 32>>>(out);
}

// round 16
// speedup vs baseline: 3.0866x; 1.0376x over previous
#include <cuda_runtime.h>
#include <cuda_fp16.h>
#include <cstdint>

#define N_      128
#define L_      1024
#define C_      512
#define LCAT_   2045
#define INV_TEMP 14.285714285714285f
#define NM_     16384
// SMEM: 3 ring stages x 48K = 147456, predC 32K @147456, total 180224
#define SMEM_FUSED 180224

__device__ float g_scr[(size_t)LCAT_ * NM_];   // logits scratch [lg][n][m]
__device__ __half g_psh[(size_t)N_ * L_ * C_];
__device__ __half g_psl[(size_t)N_ * L_ * C_];
__device__ __half g_tsh[(size_t)N_ * L_ * C_];
__device__ __half g_tsl[(size_t)N_ * L_ * C_];
__device__ __half g_wh[2][C_ * C_];            // W rounded to fp16
__device__ unsigned int g_count[2];

// ---------------------------------------------------------------------------
// Helpers (base-target PTX only)
// ---------------------------------------------------------------------------
__device__ __forceinline__ uint32_t smem_u32(const void* p) {
    uint32_t a;
    asm("{ .reg .u64 t; cvta.to.shared.u64 t, %1; cvt.u32.u64 %0, t; }"
        : "=r"(a) : "l"(p));
    return a;
}
__device__ __forceinline__ uint32_t sw128(uint32_t off) {
    return off ^ ((off >> 3) & 0x70);
}
__device__ __forceinline__ void ldsm_x4(uint32_t (&r)[4], uint32_t addr) {
    asm volatile("ldmatrix.sync.aligned.m8n8.x4.shared.b16 {%0,%1,%2,%3}, [%4];"
        : "=r"(r[0]), "=r"(r[1]), "=r"(r[2]), "=r"(r[3]) : "r"(addr));
}
__device__ __forceinline__ void mma16816(float (&d)[4], const uint32_t (&a)[4],
                                         uint32_t b0, uint32_t b1) {
    asm volatile(
        "mma.sync.aligned.m16n8k16.row.col.f32.f16.f16.f32 "
        "{%0,%1,%2,%3}, {%4,%5,%6,%7}, {%8,%9}, {%0,%1,%2,%3};"
        : "+f"(d[0]), "+f"(d[1]), "+f"(d[2]), "+f"(d[3])
        : "r"(a[0]), "r"(a[1]), "r"(a[2]), "r"(a[3]), "r"(b0), "r"(b1));
}
__device__ __forceinline__ void cpasync16(uint32_t dst, const void* src) {
    asm volatile("cp.async.cg.shared.global [%0], [%1], 16;"
                 :: "r"(dst), "l"(src) : "memory");
}
#define CP_COMMIT() asm volatile("cp.async.commit_group;" ::: "memory")
#define CP_WAIT1()  asm volatile("cp.async.wait_group 1;" ::: "memory")

// fp16 pair split: h = rn(x), l = rn(x - h)
__device__ __forceinline__ void splitp(float a, float b, uint32_t& h2, uint32_t& l2) {
    __half2 h = __floats2half2_rn(a, b);
    float2 hf = __half22float2(h);
    __half2 l = __floats2half2_rn(a - hf.x, b - hf.y);
    h2 = *reinterpret_cast<uint32_t*>(&h);
    l2 = *reinterpret_cast<uint32_t*>(&l);
}

// ===========================================================================
// Pre-split kernels
// ===========================================================================
__global__ void split_pair_k(const float* __restrict__ src,
                             __half* __restrict__ dh, __half* __restrict__ dl,
                             size_t n8)
{
    size_t u = (size_t)blockIdx.x * blockDim.x + threadIdx.x;
    if (u >= n8) return;
    const float* p = src + u * 8;
    float4 x0 = *(const float4*)p;
    float4 x1 = *(const float4*)(p + 4);
    uint32_t h0, l0, h1, l1, h2, l2, h3, l3;
    splitp(x0.x, x0.y, h0, l0);
    splitp(x0.z, x0.w, h1, l1);
    splitp(x1.x, x1.y, h2, l2);
    splitp(x1.z, x1.w, h3, l3);
    *(uint4*)(dh + u * 8) = make_uint4(h0, h1, h2, h3);
    *(uint4*)(dl + u * 8) = make_uint4(l0, l1, l2, l3);
}
__global__ void round_k(const float* __restrict__ src,
                        __half* __restrict__ dh, size_t n8)
{
    size_t u = (size_t)blockIdx.x * blockDim.x + threadIdx.x;
    if (u >= n8) return;
    const float* p = src + u * 8;
    float4 x0 = *(const float4*)p;
    float4 x1 = *(const float4*)(p + 4);
    __half2 a = __floats2half2_rn(x0.x, x0.y);
    __half2 b = __floats2half2_rn(x0.z, x0.w);
    __half2 c = __floats2half2_rn(x1.x, x1.y);
    __half2 d = __floats2half2_rn(x1.z, x1.w);
    *(uint4*)(dh + u * 8) = make_uint4(
        *reinterpret_cast<uint32_t*>(&a), *reinterpret_cast<uint32_t*>(&b),
        *reinterpret_cast<uint32_t*>(&c), *reinterpret_cast<uint32_t*>(&d));
}

// ===========================================================================
// Fused kernel, single launch for both steps. Ring of 40 items per block:
//   item it: q = it/10, r = it%10.
//   r<8 : GEMM1 chunk (A = P_l rows m, hi+lo; B = W q-chunk rows c, hi) 48KB
//   r>=8: T chunk sub=r-8 (A2 = T_(l+step) rows n, hi+lo, k=q*128+sub*64) 32KB
//   3 ring stages @ it%3 * 49152 : [AH 16K | AL 16K | BH 16K]
//   predC @ 147456: 2 sub-tiles (128m x 64c fp16, SW128) of 16K.
//   One __syncthreads per item. Empty commit groups keep wait_group aligned.
// ===========================================================================
__global__ void __launch_bounds__(256, 1)
fused_tc(const __half* __restrict__ tsh, const __half* __restrict__ tsl,
         const __half* __restrict__ psh, const __half* __restrict__ psl,
         const __half* __restrict__ whab,
         const float* __restrict__ b1, const float* __restrict__ b2)
{
    extern __shared__ char sm[];
    __shared__ float sbias[C_];
    const uint32_t u0 = smem_u32(sm);
    const int tid = threadIdx.x;

    int step, l, lofs, cntIdx;
    const float* bias;
    const __half* w;
    if (blockIdx.x < 1023) {
        step = 1; l = blockIdx.x; lofs = 0; cntIdx = 0; bias = b1; w = whab;
    } else {
        step = 2; l = blockIdx.x - 1023; lofs = 1023; cntIdx = 1; bias = b2;
        w = whab + C_ * C_;
    }
    sbias[tid] = bias[tid];
    sbias[tid + 256] = bias[tid + 256];

    const int lane = tid & 31, wid = tid >> 5;
    const int wm = wid & 3, wn = wid >> 2;
    const int rowBlk = wm * 32, colBlk = wn * 64;
    const uint32_t aRow = (uint32_t)(lane & 15);
    const uint32_t aKb  = (uint32_t)((lane >> 4) << 4);
    const uint32_t bRow = (uint32_t)((lane & 7) + ((lane >> 4) << 3));
    const uint32_t bKb  = (uint32_t)(((lane >> 3) & 1) << 4);
    const int tr = lane >> 2, tc = lane & 3;

    const size_t rowStr = (size_t)L_ * C_;
    const uint32_t uPC = u0 + 147456u;

    // Issue ring item (always commits a group, possibly empty, to keep count)
    auto issue_item = [&](int it) {
        if (it < 40) {
            const int q = it / 10, r = it % 10;
            const uint32_t sb = u0 + (uint32_t)(it % 3) * 49152u;
            if (r < 8) {
#pragma unroll
                for (int t = 0; t < 4; t++) {
                    int u = tid + t * 256;
                    int rr = u >> 3, cu = u & 7;
                    uint32_t d = sw128((uint32_t)(rr * 128 + cu * 16));
                    size_t ga = (size_t)rr * rowStr + (size_t)l * C_ + r * 64 + cu * 8;
                    cpasync16(sb + d, psh + ga);
                    cpasync16(sb + 16384u + d, psl + ga);
                    size_t gb = (size_t)(q * 128 + rr) * C_ + r * 64 + cu * 8;
                    cpasync16(sb + 32768u + d, w + gb);
                }
            } else {
                const int sub = r - 8;
#pragma unroll
                for (int t = 0; t < 4; t++) {
                    int u = tid + t * 256;
                    int rr = u >> 3, cu = u & 7;
                    uint32_t d = sw128((uint32_t)(rr * 128 + cu * 16));
                    size_t ga = (size_t)rr * rowStr + (size_t)(l + step) * C_
                              + q * 128 + sub * 64 + cu * 8;
                    cpasync16(sb + d, tsh + ga);
                    cpasync16(sb + 16384u + d, tsl + ga);
                }
            }
        }
        CP_COMMIT();
    };

    float cL[2][8][4];
#pragma unroll
    for (int i = 0; i < 2; i++)
#pragma unroll
        for (int j = 0; j < 8; j++)
#pragma unroll
            for (int k = 0; k < 4; k++) cL[i][j][k] = 0.0f;

    float cP[2][8][4];

    issue_item(0);
    issue_item(1);

    for (int it = 0; it < 40; it++) {
        const int q = it / 10, r = it % 10;
        CP_WAIT1();
        __syncthreads();
        const uint32_t sb = u0 + (uint32_t)(it % 3) * 49152u;

        if (r < 8) {
            if (r == 0) {
#pragma unroll
                for (int i = 0; i < 2; i++)
#pragma unroll
                    for (int j = 0; j < 8; j++)
#pragma unroll
                        for (int k = 0; k < 4; k++) cP[i][j][k] = 0.0f;
            }
            const uint32_t uAH = sb, uAL = sb + 16384u, uBH = sb + 32768u;
#pragma unroll
            for (int ks = 0; ks < 4; ks++) {
                const uint32_t kb0 = (uint32_t)(ks * 32);
                uint32_t ah[2][4], al[2][4];
#pragma unroll
                for (int mi = 0; mi < 2; mi++) {
                    uint32_t off = sw128((uint32_t)(rowBlk + mi * 16 + aRow) * 128 + kb0 + aKb);
                    ldsm_x4(ah[mi], uAH + off);
                    ldsm_x4(al[mi], uAL + off);
                }
#pragma unroll
                for (int ng = 0; ng < 4; ng++) {
                    uint32_t boff = sw128((uint32_t)(colBlk + ng * 16 + bRow) * 128 + kb0 + bKb);
                    uint32_t bh[4];
                    ldsm_x4(bh, uBH + boff);
#pragma unroll
                    for (int mi = 0; mi < 2; mi++) {
                        mma16816(cP[mi][2 * ng],     ah[mi], bh[0], bh[1]);
                        mma16816(cP[mi][2 * ng],     al[mi], bh[0], bh[1]);
                        mma16816(cP[mi][2 * ng + 1], ah[mi], bh[2], bh[3]);
                        mma16816(cP[mi][2 * ng + 1], al[mi], bh[2], bh[3]);
                    }
                }
            }
        } else {
            if (r == 8) {
                // Epilogue1: +bias -> fp16 predC sub-tiles (sub = wn)
                char* pc = sm + 147456;
                const int sb16 = wn * 16384;
#pragma unroll
                for (int mi = 0; mi < 2; mi++) {
                    const int m0r = rowBlk + mi * 16 + tr;
#pragma unroll
                    for (int ni = 0; ni < 8; ni++) {
                        const int cin = ni * 8 + 2 * tc;
                        const float b0v = sbias[q * 128 + colBlk + cin];
                        const float b1v = sbias[q * 128 + colBlk + cin + 1];
                        __half2 ha = __floats2half2_rn(cP[mi][ni][0] + b0v, cP[mi][ni][1] + b1v);
                        __half2 hb = __floats2half2_rn(cP[mi][ni][2] + b0v, cP[mi][ni][3] + b1v);
                        uint32_t o0 = sw128((uint32_t)(m0r * 128 + cin * 2));
                        uint32_t o1 = sw128((uint32_t)((m0r + 8) * 128 + cin * 2));
                        *(uint32_t*)(pc + sb16 + o0) = *reinterpret_cast<uint32_t*>(&ha);
                        *(uint32_t*)(pc + sb16 + o1) = *reinterpret_cast<uint32_t*>(&hb);
                    }
                }
                __syncthreads();
            }
            // GEMM2: cL += T_sub . predC_sub^T  (k = 64)
            const int sub = r - 8;
            const uint32_t uTh = sb, uTl = sb + 16384u;
            const uint32_t uB  = uPC + (uint32_t)sub * 16384u;
#pragma unroll
            for (int ks = 0; ks < 4; ks++) {
                const uint32_t kb0 = (uint32_t)(ks * 32);
                uint32_t ah[2][4], al[2][4];
#pragma unroll
                for (int mi = 0; mi < 2; mi++) {
                    uint32_t off = sw128((uint32_t)(rowBlk + mi * 16 + aRow) * 128 + kb0 + aKb);
                    ldsm_x4(ah[mi], uTh + off);
                    ldsm_x4(al[mi], uTl + off);
                }
#pragma unroll
                for (int ng = 0; ng < 4; ng++) {
                    uint32_t boff = sw128((uint32_t)(colBlk + ng * 16 + bRow) * 128 + kb0 + bKb);
                    uint32_t bh[4];
                    ldsm_x4(bh, uB + boff);
#pragma unroll
                    for (int mi = 0; mi < 2; mi++) {
                        mma16816(cL[mi][2 * ng],     ah[mi], bh[0], bh[1]);
                        mma16816(cL[mi][2 * ng],     al[mi], bh[0], bh[1]);
                        mma16816(cL[mi][2 * ng + 1], ah[mi], bh[2], bh[3]);
                        mma16816(cL[mi][2 * ng + 1], al[mi], bh[2], bh[3]);
                    }
                }
            }
        }
        issue_item(it + 2);
    }

    // ---- Final epilogue: dump cL, NCE accuracy, scaled scratch store ----
    __syncthreads();
    float* s = (float*)sm;
#pragma unroll
    for (int mi = 0; mi < 2; mi++) {
        const int row = rowBlk + mi * 16 + tr;
#pragma unroll
        for (int ni = 0; ni < 8; ni++) {
            const int col = colBlk + ni * 8 + 2 * tc;
            *(float2*)&s[row * 130 + col]       = make_float2(cL[mi][ni][0], cL[mi][ni][1]);
            *(float2*)&s[(row + 8) * 130 + col] = make_float2(cL[mi][ni][2], cL[mi][ni][3]);
        }
    }
    __syncthreads();

    if (tid < 128) {
        const float pos = s[tid * 130 + tid];
        bool ok = true;
#pragma unroll 8
        for (int j = 0; j < 128; j++) ok &= (j == tid) || (pos > s[tid * 130 + j]);
        unsigned bal = __ballot_sync(0xFFFFFFFFu, ok);
        if ((tid & 31) == 0) atomicAdd(&g_count[cntIdx], (unsigned)__popc(bal));
    }

    float* dst = g_scr + (size_t)(lofs + l) * NM_;
#pragma unroll 8
    for (int idx = tid; idx < NM_; idx += 256)
        dst[idx] = s[(idx >> 7) * 130 + (idx & 127)] * INV_TEMP;
}

// ===========================================================================
// Transpose / init / finalize
// ===========================================================================
__global__ void transpose_k(float* __restrict__ out)
{
    __shared__ float t[32][33];
    const int l0 = blockIdx.x * 32, p0 = blockIdx.y * 32;
    const int x = threadIdx.x, y = threadIdx.y;
#pragma unroll
    for (int i = y; i < 32; i += 8) {
        int lg = l0 + i;
        t[i][x] = (lg < LCAT_) ? g_scr[(size_t)lg * NM_ + (p0 + x)] : 0.0f;
    }
    __syncthreads();
#pragma unroll
    for (int i = y; i < 32; i += 8) {
        int lg = l0 + x;
        if (lg < LCAT_)
            out[(size_t)(p0 + i) * LCAT_ + lg] = t[x][i];
    }
}
__global__ void init_kernel(float* __restrict__ out)
{
    if (blockIdx.x == 0 && threadIdx.x < 2) g_count[threadIdx.x] = 0u;
    const size_t idx = (size_t)blockIdx.x * 256 + threadIdx.x;
    if (idx < (size_t)N_ * LCAT_) {
        const size_t basep = (size_t)N_ * N_ * LCAT_;
        out[basep + idx] = (float)(idx / LCAT_);
    }
}
__global__ void fin_kernel(float* __restrict__ out)
{
    if (threadIdx.x == 0) {
        const size_t basep = (size_t)N_ * N_ * LCAT_ + (size_t)N_ * LCAT_;
        out[basep + 0] = (float)g_count[0] / (float)(N_ * 1023);
        out[basep + 1] = (float)g_count[1] / (float)(N_ * 1022);
    }
}

// ---------------------------------------------------------------------------
// Launch
// ---------------------------------------------------------------------------
extern "C" void kernel_launch(void* const* d_in, const int* in_sizes, int n_in,
                              void* d_out, int out_size)
{
    const float* ts = (const float*)d_in[0];
    const float* ps = (const float*)d_in[1];
    const float* W1 = (const float*)d_in[2];
    const float* b1 = (const float*)d_in[3];
    const float* W2 = (const float*)d_in[4];
    const float* b2 = (const float*)d_in[5];
    float* out = (float*)d_out;

    cudaFuncSetAttribute(fused_tc, cudaFuncAttributeMaxDynamicSharedMemorySize, SMEM_FUSED);

    init_kernel<<<1023, 256>>>(out);

    __half *psh, *psl, *tsh, *tsl, *whab;
    cudaGetSymbolAddress((void**)&psh, g_psh);
    cudaGetSymbolAddress((void**)&psl, g_psl);
    cudaGetSymbolAddress((void**)&tsh, g_tsh);
    cudaGetSymbolAddress((void**)&tsl, g_tsl);
    {
        void* p;
        cudaGetSymbolAddress(&p, g_wh);
        whab = (__half*)p;
    }
    const size_t n8 = (size_t)N_ * L_ * C_ / 8;
    split_pair_k<<<(unsigned)((n8 + 255) / 256), 256>>>(ps, psh, psl, n8);
    split_pair_k<<<(unsigned)((n8 + 255) / 256), 256>>>(ts, tsh, tsl, n8);
    const size_t n8w = (size_t)C_ * C_ / 8;
    round_k<<<(unsigned)((n8w + 255) / 256), 256>>>(W1, whab, n8w);
    round_k<<<(unsigned)((n8w + 255) / 256), 256>>>(W2, whab + C_ * C_, n8w);

    fused_tc<<<2045, 256, SMEM_FUSED>>>(tsh, tsl, psh, psl, whab, b1, b2);

    dim3 gt(64, 512), bt(32, 8);
    transpose_k<<<gt, bt>>>(out);
    fin_kernel<<<1, 32>>>(out);
}